// round 6
// baseline (speedup 1.0000x reference)
#include <cuda_runtime.h>
#include <cuda_bf16.h>
#include <math.h>
#include <stdint.h>

// ---------------------------------------------------------------------------
// Problem constants
// ---------------------------------------------------------------------------
#define BB 2
#define SS 4096
#define HH 16
#define DKQV 2048
#define DH 128
#define DRH 64
#define MTOK (BB*SS)            // 8192 tokens

// ---------------------------------------------------------------------------
// Device scratch
// ---------------------------------------------------------------------------
__device__ float g_s1 [MTOK * 2048];   // cq | ckv | kr
__device__ float g_s2 [MTOK * 3072];   // q | qr
__device__ float g_s3 [MTOK * 4096];   // k | v
__device__ float g_ob [MTOK * 2048];   // attention out
__device__ __nv_bfloat16 g_w1h[2048 * 2048], g_w1l[2048 * 2048];
__device__ __nv_bfloat16 g_w2h[3072 * 512],  g_w2l[3072 * 512];
__device__ __nv_bfloat16 g_w3h[4096 * 512],  g_w3l[4096 * 512];
__device__ __nv_bfloat16 g_w4h[2048 * 2048], g_w4l[2048 * 2048];
__device__ float g_b1 [2048];
__device__ float g_b2 [3072];
__device__ float g_b3 [4096];

// ---------------------------------------------------------------------------
// GEMM config: CTA 128(M)x256(N), BK=32, 256 threads (8 warps, 2Mx4N of 64x64)
// A smem fp32 [128][40]; B smem bf16x2 u32 [256][20] (hi and lo). 3 stages.
// ---------------------------------------------------------------------------
#define BM 128
#define BN 256
#define BK 32
#define ASTRIDE 40
#define BSTRIDE 20
#define A_TILE_B (128 * ASTRIDE * 4)          // 20480
#define B_TILE_B (256 * BSTRIDE * 4)          // 20480
#define STAGE_B (A_TILE_B + 2 * B_TILE_B)     // 61440
#define NSTAGE 3
#define SMEM_BYTES (NSTAGE * STAGE_B)         // 184320

__device__ __forceinline__ uint32_t smem_u32(const void* p) {
    uint32_t a;
    asm("{ .reg .u64 t; cvta.to.shared.u64 t, %1; cvt.u32.u64 %0, t; }"
        : "=r"(a) : "l"(p));
    return a;
}
__device__ __forceinline__ void cp_async16(uint32_t dst, const void* src) {
    asm volatile("cp.async.cg.shared.global [%0], [%1], 16;"
                 :: "r"(dst), "l"(src) : "memory");
}
__device__ __forceinline__ void cp_commit() {
    asm volatile("cp.async.commit_group;" ::: "memory");
}
__device__ __forceinline__ void cp_wait2() {
    asm volatile("cp.async.wait_group 2;" ::: "memory");
}

__device__ __forceinline__ void mma_bf16(float c[4], uint32_t a0, uint32_t a1,
                                         uint32_t a2, uint32_t a3,
                                         uint32_t b0, uint32_t b1) {
    asm volatile(
        "mma.sync.aligned.m16n8k16.row.col.f32.bf16.bf16.f32 "
        "{%0,%1,%2,%3}, {%4,%5,%6,%7}, {%8,%9}, {%0,%1,%2,%3};"
        : "+f"(c[0]), "+f"(c[1]), "+f"(c[2]), "+f"(c[3])
        : "r"(a0), "r"(a1), "r"(a2), "r"(a3), "r"(b0), "r"(b1));
}

// Split two fp32 into packed bf16x2 hi + lo (lo = x - float(hi))
__device__ __forceinline__ void split_pair(float x0, float x1,
                                           uint32_t& h, uint32_t& l) {
    asm("cvt.rn.bf16x2.f32 %0, %1, %2;" : "=r"(h) : "f"(x1), "f"(x0));
    float h0 = __uint_as_float(h << 16);
    float h1 = __uint_as_float(h & 0xFFFF0000u);
    float l0 = x0 - h0, l1 = x1 - h1;
    asm("cvt.rn.bf16x2.f32 %0, %1, %2;" : "=r"(l) : "f"(l1), "f"(l0));
}

// A: 128x32 fp32 tile (row-major, ld) -> smem [128][40]; 256 threads
__device__ __forceinline__ void tileA_async(const float* __restrict__ g, int ld,
                                            uint32_t sbase, int tid) {
#pragma unroll
    for (int j = 0; j < 4; j++) {
        int idx = tid + j * 256;      // 0..1023
        int r = idx >> 3, c = idx & 7;
        cp_async16(sbase + (uint32_t)(r * ASTRIDE + c * 4) * 4,
                   g + (size_t)r * ld + c * 4);
    }
}
// B: 256x32 bf16 tile ([N,K] row-major, ld=K) -> smem u32 [256][20]; 256 thr
__device__ __forceinline__ void tileB_async(const __nv_bfloat16* __restrict__ g,
                                            int ld, uint32_t sbase, int tid) {
#pragma unroll
    for (int j = 0; j < 4; j++) {
        int idx = tid + j * 256;      // 0..1023
        int r = idx >> 2, c = idx & 3;
        cp_async16(sbase + (uint32_t)(r * BSTRIDE + c * 4) * 4,
                   g + (size_t)r * ld + c * 8);
    }
}

// ---------------------------------------------------------------------------
// bf16x3 GEMM: C[M,N] = A[M,K](fp32,lda) @ (Bh+Bl)[N,K]^T + bias
// grid(N/256, M/128), 256 threads
// ---------------------------------------------------------------------------
__global__ void __launch_bounds__(256, 1) gemm_bf16x3_kernel(
    const float* __restrict__ A, int lda,
    const __nv_bfloat16* __restrict__ Bh,
    const __nv_bfloat16* __restrict__ Bl,
    const float* __restrict__ bias,
    float* __restrict__ C,
    int M, int N, int K)
{
    extern __shared__ float smem[];
    const uint32_t sb = smem_u32(smem);
    const int tid = threadIdx.x;
    const int wid = tid >> 5;
    const int lane = tid & 31;
    const int g = lane >> 2;
    const int t = lane & 3;
    const int wm = (wid & 1) * 64;     // 2 warps in M
    const int wn = (wid >> 1) * 64;    // 4 warps in N

    const int m0 = blockIdx.y * BM;
    const int n0 = blockIdx.x * BN;
    const float* Abase = A + (size_t)m0 * lda;
    const __nv_bfloat16* BhBase = Bh + (size_t)n0 * K;
    const __nv_bfloat16* BlBase = Bl + (size_t)n0 * K;

    float acc[4][8][4];
#pragma unroll
    for (int mf = 0; mf < 4; mf++)
#pragma unroll
        for (int nf = 0; nf < 8; nf++)
#pragma unroll
            for (int r = 0; r < 4; r++) acc[mf][nf][r] = 0.f;

    const int NC = K / BK;

    // Prologue: stages 0,1,2
#pragma unroll
    for (int p = 0; p < 3; p++) {
        const uint32_t st = sb + p * STAGE_B;
        tileA_async(Abase + p * BK, lda, st, tid);
        tileB_async(BhBase + p * BK, K, st + A_TILE_B, tid);
        tileB_async(BlBase + p * BK, K, st + A_TILE_B + B_TILE_B, tid);
        cp_commit();
    }

    int s = 0;
    for (int i = 0; i < NC; i++) {
        cp_wait2();
        __syncthreads();
        const uint32_t st = sb + s * STAGE_B;
        const float* As = smem + (st - sb) / 4;
        const uint32_t* BsH = (const uint32_t*)smem + (st + A_TILE_B - sb) / 4;
        const uint32_t* BsL = (const uint32_t*)smem + (st + A_TILE_B + B_TILE_B - sb) / 4;

#pragma unroll
        for (int ks = 0; ks < 2; ks++) {       // two k16 steps
            const int kc = ks * 16;
            uint32_t ah[4][4], al[4][4];
#pragma unroll
            for (int mf = 0; mf < 4; mf++) {
                const float* ap  = As + (wm + mf * 16 + g) * ASTRIDE + kc + 2 * t;
                const float* ap8 = ap + 8 * ASTRIDE;
                split_pair(ap [0], ap [1], ah[mf][0], al[mf][0]);
                split_pair(ap8[0], ap8[1], ah[mf][1], al[mf][1]);
                split_pair(ap [8], ap [9], ah[mf][2], al[mf][2]);
                split_pair(ap8[8], ap8[9], ah[mf][3], al[mf][3]);
            }
            uint32_t bh[8][2], bl[8][2];
#pragma unroll
            for (int nf = 0; nf < 8; nf++) {
                const int rb = (wn + nf * 8 + g) * BSTRIDE + ks * 8 + t;
                bh[nf][0] = BsH[rb];
                bh[nf][1] = BsH[rb + 4];
                bl[nf][0] = BsL[rb];
                bl[nf][1] = BsL[rb + 4];
            }
#pragma unroll
            for (int mf = 0; mf < 4; mf++)
#pragma unroll
                for (int nf = 0; nf < 8; nf++) {
                    mma_bf16(acc[mf][nf], ah[mf][0], ah[mf][1], ah[mf][2],
                             ah[mf][3], bh[nf][0], bh[nf][1]);
                    mma_bf16(acc[mf][nf], ah[mf][0], ah[mf][1], ah[mf][2],
                             ah[mf][3], bl[nf][0], bl[nf][1]);
                    mma_bf16(acc[mf][nf], al[mf][0], al[mf][1], al[mf][2],
                             al[mf][3], bh[nf][0], bh[nf][1]);
                }
        }
        __syncthreads();
        if (i + 3 < NC) {
            const int k0 = (i + 3) * BK;
            const uint32_t st2 = sb + s * STAGE_B;
            tileA_async(Abase + k0, lda, st2, tid);
            tileB_async(BhBase + k0, K, st2 + A_TILE_B, tid);
            tileB_async(BlBase + k0, K, st2 + A_TILE_B + B_TILE_B, tid);
        }
        cp_commit();
        s = (s + 1 == NSTAGE) ? 0 : s + 1;
    }

    // Epilogue
#pragma unroll
    for (int mf = 0; mf < 4; mf++) {
        const int row0 = m0 + wm + mf * 16 + g;
#pragma unroll
        for (int nf = 0; nf < 8; nf++) {
            const int col = n0 + wn + nf * 8 + 2 * t;
            const float b0 = bias[col], b1 = bias[col + 1];
            float2 v0 = { acc[mf][nf][0] + b0, acc[mf][nf][1] + b1 };
            float2 v1 = { acc[mf][nf][2] + b0, acc[mf][nf][3] + b1 };
            *(float2*)(C + (size_t)row0 * N + col) = v0;
            *(float2*)(C + (size_t)(row0 + 8) * N + col) = v1;
        }
    }
}

// ---------------------------------------------------------------------------
// Transpose + bf16 hi/lo split: src[rows,cols] fp32 -> hi/lo[cols,rows] bf16
// ---------------------------------------------------------------------------
__global__ void transpose_split(const float* __restrict__ src,
                                __nv_bfloat16* __restrict__ hi,
                                __nv_bfloat16* __restrict__ lo,
                                int rows, int cols)
{
    __shared__ float tile[32][33];
    const int c0 = blockIdx.x * 32, r0 = blockIdx.y * 32;
    for (int i = threadIdx.y; i < 32; i += 8)
        tile[i][threadIdx.x] = src[(size_t)(r0 + i) * cols + c0 + threadIdx.x];
    __syncthreads();
    for (int i = threadIdx.y; i < 32; i += 8) {
        float x = tile[threadIdx.x][i];
        __nv_bfloat16 h = __float2bfloat16_rn(x);
        __nv_bfloat16 l = __float2bfloat16_rn(x - __bfloat162float(h));
        size_t o = (size_t)(c0 + i) * rows + r0 + threadIdx.x;
        hi[o] = h;
        lo[o] = l;
    }
}

__global__ void copyf(const float* __restrict__ s, float* __restrict__ d, int n)
{
    int i = blockIdx.x * 256 + threadIdx.x;
    if (i < n) d[i] = s[i];
}

// ---------------------------------------------------------------------------
// Per-token attention (rope fused). 256 threads / token.
// ---------------------------------------------------------------------------
#define QK_STRIDE 193

__global__ void __launch_bounds__(256) attn_kernel(
    const float* __restrict__ s1, const float* __restrict__ s2,
    const float* __restrict__ s3, float* __restrict__ obuf)
{
    const float SCALER = 1.0f / sqrtf((float)(DH + DRH));
    const float LOG1E4 = 9.210340371976184f;

    int tk = blockIdx.x;
    int s = tk & (SS - 1);
    int tid = threadIdx.x;

    __shared__ float qf[HH][QK_STRIDE];
    __shared__ float kf[HH][QK_STRIDE];
    __shared__ float vv[HH][DH];
    __shared__ float sc[HH][HH];
    __shared__ float at[HH][HH];

    const float* qp  = s2 + (size_t)tk * 3072;
    const float* qrp = qp + 2048;
    const float* kp  = s3 + (size_t)tk * 4096;
    const float* vp  = kp + 2048;
    const float* krp = s1 + (size_t)tk * 2048 + 1024;

    for (int idx = tid; idx < HH * DH; idx += 256) {
        int h = idx >> 7, d = idx & 127;
        qf[h][d] = qp[idx];
        kf[h][d] = kp[idx];
        vv[h][d] = vp[idx];
    }
    for (int idx = tid; idx < HH * 32; idx += 256) {
        int h = idx >> 5, j = idx & 31;
        float invf = expf(-LOG1E4 * ((float)(2 * j) / 64.0f));
        float ang = (float)s * invf;
        float sj, cj;
        sincosf(ang, &sj, &cj);
        float x1q = qrp[h * DRH + j], x2q = qrp[h * DRH + j + 32];
        qf[h][DH + j]      = x1q * cj - x2q * sj;
        qf[h][DH + j + 32] = x2q * cj + x1q * sj;
        float x1k = krp[h * DRH + j], x2k = krp[h * DRH + j + 32];
        kf[h][DH + j]      = x1k * cj - x2k * sj;
        kf[h][DH + j + 32] = x2k * cj + x1k * sj;
    }
    __syncthreads();

    {
        int i = tid >> 4, j = tid & 15;
        float dsum = 0.f;
#pragma unroll 8
        for (int d = 0; d < DH + DRH; d++)
            dsum = fmaf(qf[i][d], kf[j][d], dsum);
        sc[i][j] = dsum * SCALER;
    }
    __syncthreads();

    if (tid < HH) {
        float mx = -1e30f;
#pragma unroll
        for (int j = 0; j < HH; j++) mx = fmaxf(mx, sc[tid][j]);
        float e[HH], sum = 0.f;
#pragma unroll
        for (int j = 0; j < HH; j++) { e[j] = expf(sc[tid][j] - mx); sum += e[j]; }
        float inv = 1.0f / sum;
#pragma unroll
        for (int j = 0; j < HH; j++) at[tid][j] = e[j] * inv;
    }
    __syncthreads();

    float* op = obuf + (size_t)tk * DKQV;
    for (int idx = tid; idx < HH * DH; idx += 256) {
        int i = idx >> 7, d = idx & 127;
        float acc = 0.f;
#pragma unroll
        for (int j = 0; j < HH; j++)
            acc = fmaf(at[i][j], vv[j][d], acc);
        op[idx] = acc;
    }
}

// ---------------------------------------------------------------------------
// Launch
// ---------------------------------------------------------------------------
static void launch_gemm(const float* A, int lda, const __nv_bfloat16* Bh,
                        const __nv_bfloat16* Bl, const float* bias,
                        float* C, int M, int N, int K)
{
    cudaFuncSetAttribute(gemm_bf16x3_kernel,
                         cudaFuncAttributeMaxDynamicSharedMemorySize, SMEM_BYTES);
    dim3 grid(N / BN, M / BM);
    gemm_bf16x3_kernel<<<grid, 256, SMEM_BYTES>>>(A, lda, Bh, Bl, bias, C, M, N, K);
}

static void launch_tsplit(const float* src, __nv_bfloat16* hi, __nv_bfloat16* lo,
                          int rows, int cols)
{
    dim3 grid(cols / 32, rows / 32), blk(32, 8);
    transpose_split<<<grid, blk>>>(src, hi, lo, rows, cols);
}

static void launch_copy(const float* s, float* d, int n)
{
    copyf<<<(n + 255) / 256, 256>>>(s, d, n);
}

extern "C" void kernel_launch(void* const* d_in, const int* in_sizes, int n_in,
                              void* d_out, int out_size)
{
    const float* h_t  = (const float*)d_in[0];
    const float* Wc   = (const float*)d_in[1];
    const float* bc   = (const float*)d_in[2];
    const float* Wcq  = (const float*)d_in[3];
    const float* bcq  = (const float*)d_in[4];
    const float* Wqr  = (const float*)d_in[5];
    const float* bqr  = (const float*)d_in[6];
    const float* Wckv = (const float*)d_in[7];
    const float* bckv = (const float*)d_in[8];
    const float* Wck  = (const float*)d_in[9];
    const float* bck  = (const float*)d_in[10];
    const float* Wkr  = (const float*)d_in[11];
    const float* bkr  = (const float*)d_in[12];
    const float* Wv   = (const float*)d_in[13];
    const float* bv   = (const float*)d_in[14];
    const float* Wo   = (const float*)d_in[15];
    const float* bo   = (const float*)d_in[16];
    float* out = (float*)d_out;

    float *s1, *s2, *s3, *ob, *b1, *b2, *b3;
    __nv_bfloat16 *w1h, *w1l, *w2h, *w2l, *w3h, *w3l, *w4h, *w4l;
    cudaGetSymbolAddress((void**)&s1,  g_s1);
    cudaGetSymbolAddress((void**)&s2,  g_s2);
    cudaGetSymbolAddress((void**)&s3,  g_s3);
    cudaGetSymbolAddress((void**)&ob,  g_ob);
    cudaGetSymbolAddress((void**)&w1h, g_w1h);
    cudaGetSymbolAddress((void**)&w1l, g_w1l);
    cudaGetSymbolAddress((void**)&w2h, g_w2h);
    cudaGetSymbolAddress((void**)&w2l, g_w2l);
    cudaGetSymbolAddress((void**)&w3h, g_w3h);
    cudaGetSymbolAddress((void**)&w3l, g_w3l);
    cudaGetSymbolAddress((void**)&w4h, g_w4h);
    cudaGetSymbolAddress((void**)&w4l, g_w4l);
    cudaGetSymbolAddress((void**)&b1,  g_b1);
    cudaGetSymbolAddress((void**)&b2,  g_b2);
    cudaGetSymbolAddress((void**)&b3,  g_b3);

    // Pack: transpose + hi/lo split of all weights into [N,K] bf16
    launch_tsplit(Wc,   w1h + (size_t)0    * 2048, w1l + (size_t)0    * 2048, 2048, 512);
    launch_tsplit(Wckv, w1h + (size_t)512  * 2048, w1l + (size_t)512  * 2048, 2048, 512);
    launch_tsplit(Wkr,  w1h + (size_t)1024 * 2048, w1l + (size_t)1024 * 2048, 2048, 1024);
    launch_tsplit(Wcq,  w2h + (size_t)0    * 512,  w2l + (size_t)0    * 512,  512, 2048);
    launch_tsplit(Wqr,  w2h + (size_t)2048 * 512,  w2l + (size_t)2048 * 512,  512, 1024);
    launch_tsplit(Wck,  w3h + (size_t)0    * 512,  w3l + (size_t)0    * 512,  512, 2048);
    launch_tsplit(Wv,   w3h + (size_t)2048 * 512,  w3l + (size_t)2048 * 512,  512, 2048);
    launch_tsplit(Wo,   w4h, w4l, 2048, 2048);
    launch_copy(bc,   b1,        512);
    launch_copy(bckv, b1 + 512,  512);
    launch_copy(bkr,  b1 + 1024, 1024);
    launch_copy(bcq,  b2,        2048);
    launch_copy(bqr,  b2 + 2048, 1024);
    launch_copy(bck,  b3,        2048);
    launch_copy(bv,   b3 + 2048, 2048);

    // G1: h_t -> (cq|ckv|kr)
    launch_gemm(h_t, 2048, w1h, w1l, b1, s1, MTOK, 2048, 2048);
    // G2: cq -> (q|qr)
    launch_gemm(s1, 2048, w2h, w2l, b2, s2, MTOK, 3072, 512);
    // G3: ckv -> (k|v)
    launch_gemm(s1 + 512, 2048, w3h, w3l, b3, s3, MTOK, 4096, 512);
    // attention
    attn_kernel<<<MTOK, 256>>>(s1, s2, s3, ob);
    // G4: o -> out
    launch_gemm(ob, 2048, w4h, w4l, bo, out, MTOK, 2048, 2048);
}

// round 7
// speedup vs baseline: 1.0914x; 1.0914x over previous
#include <cuda_runtime.h>
#include <cuda_bf16.h>
#include <math.h>
#include <stdint.h>

// ---------------------------------------------------------------------------
// Problem constants
// ---------------------------------------------------------------------------
#define BB 2
#define SS 4096
#define HH 16
#define DKQV 2048
#define DH 128
#define DRH 64
#define MTOK (BB*SS)            // 8192 tokens

// ---------------------------------------------------------------------------
// Device scratch
// ---------------------------------------------------------------------------
__device__ float g_s1 [MTOK * 2048];                       // cq | ckv | kr (fp32)
__device__ __nv_bfloat16 g_s1h[MTOK * 2048], g_s1l[MTOK * 2048];
__device__ float g_s2 [MTOK * 3072];                       // q | qr
__device__ float g_s3 [MTOK * 4096];                       // k | v
__device__ __nv_bfloat16 g_hth[MTOK * 2048], g_htl[MTOK * 2048];  // h_t split
__device__ __nv_bfloat16 g_obh[MTOK * 2048], g_obl[MTOK * 2048];  // attn out split
__device__ __nv_bfloat16 g_w1h[2048 * 2048], g_w1l[2048 * 2048];
__device__ __nv_bfloat16 g_w2h[3072 * 512],  g_w2l[3072 * 512];
__device__ __nv_bfloat16 g_w3h[4096 * 512],  g_w3l[4096 * 512];
__device__ __nv_bfloat16 g_w4h[2048 * 2048], g_w4l[2048 * 2048];
__device__ float g_b1 [2048];
__device__ float g_b2 [3072];
__device__ float g_b3 [4096];

// ---------------------------------------------------------------------------
// GEMM config: CTA 128x128, BK=32, 128 threads (4 warps of 64x64), 2 stages
// All operand tiles bf16 [128 rows][32 k] in smem, row stride 20 u32
// (16 data u32 + 4 pad  ->  20g+t covers all 32 banks: conflict-free)
// ---------------------------------------------------------------------------
#define BM 128
#define BN 128
#define BK 32
#define TSTRIDE 20
#define TILE_B (128 * TSTRIDE * 4)      // 10240 bytes
#define STAGE_B (4 * TILE_B)            // Ah, Al, Bh, Bl = 40960
#define SMEM_BYTES (2 * STAGE_B)        // 81920 -> 2 CTAs/SM

__device__ __forceinline__ uint32_t smem_u32(const void* p) {
    uint32_t a;
    asm("{ .reg .u64 t; cvta.to.shared.u64 t, %1; cvt.u32.u64 %0, t; }"
        : "=r"(a) : "l"(p));
    return a;
}
__device__ __forceinline__ void cp_async16(uint32_t dst, const void* src) {
    asm volatile("cp.async.cg.shared.global [%0], [%1], 16;"
                 :: "r"(dst), "l"(src) : "memory");
}
__device__ __forceinline__ void cp_commit() {
    asm volatile("cp.async.commit_group;" ::: "memory");
}
__device__ __forceinline__ void cp_wait1() {
    asm volatile("cp.async.wait_group 1;" ::: "memory");
}

__device__ __forceinline__ void mma_bf16(float c[4], uint32_t a0, uint32_t a1,
                                         uint32_t a2, uint32_t a3,
                                         uint32_t b0, uint32_t b1) {
    asm volatile(
        "mma.sync.aligned.m16n8k16.row.col.f32.bf16.bf16.f32 "
        "{%0,%1,%2,%3}, {%4,%5,%6,%7}, {%8,%9}, {%0,%1,%2,%3};"
        : "+f"(c[0]), "+f"(c[1]), "+f"(c[2]), "+f"(c[3])
        : "r"(a0), "r"(a1), "r"(a2), "r"(a3), "r"(b0), "r"(b1));
}

// bf16 [row,K] tile (128 rows x 32 cols = 64B/row) -> smem [128][20 u32]
__device__ __forceinline__ void tile_async(const __nv_bfloat16* __restrict__ g,
                                           int ld, uint32_t sbase, int tid) {
#pragma unroll
    for (int j = 0; j < 4; j++) {
        int idx = tid + j * 128;       // 0..511
        int r = idx >> 2, c = idx & 3; // 4 x 16B chunks per row
        cp_async16(sbase + (uint32_t)(r * TSTRIDE + c * 4) * 4,
                   g + (size_t)r * ld + c * 8);
    }
}

// ---------------------------------------------------------------------------
// bf16x3 GEMM: C = (Ah+Al)[M,K] @ (Bh+Bl)[N,K]^T + bias
// Optionally also emits hi/lo bf16 copies of C (for the next GEMM's A).
// grid(N/128, M/128), 128 threads
// ---------------------------------------------------------------------------
__global__ void __launch_bounds__(128, 2) gemm_bf16x3_kernel(
    const __nv_bfloat16* __restrict__ Ah,
    const __nv_bfloat16* __restrict__ Al, int lda,
    const __nv_bfloat16* __restrict__ Bh,
    const __nv_bfloat16* __restrict__ Bl,
    const float* __restrict__ bias,
    float* __restrict__ C,
    __nv_bfloat16* __restrict__ Ch,       // may be null
    __nv_bfloat16* __restrict__ Cl,
    int M, int N, int K)
{
    extern __shared__ float smem[];
    const uint32_t sb = smem_u32(smem);
    const uint32_t* Su = (const uint32_t*)smem;
    const int tid = threadIdx.x;
    const int wid = tid >> 5;
    const int lane = tid & 31;
    const int g = lane >> 2;
    const int t = lane & 3;
    const int wm = (wid & 1) * 64;
    const int wn = (wid >> 1) * 64;

    const int m0 = blockIdx.y * BM;
    const int n0 = blockIdx.x * BN;
    const __nv_bfloat16* AhB = Ah + (size_t)m0 * lda;
    const __nv_bfloat16* AlB = Al + (size_t)m0 * lda;
    const __nv_bfloat16* BhB = Bh + (size_t)n0 * K;
    const __nv_bfloat16* BlB = Bl + (size_t)n0 * K;

    float acc[4][8][4];
#pragma unroll
    for (int mf = 0; mf < 4; mf++)
#pragma unroll
        for (int nf = 0; nf < 8; nf++)
#pragma unroll
            for (int r = 0; r < 4; r++) acc[mf][nf][r] = 0.f;

    const int NC = K / BK;

    // Prologue: stages 0,1
#pragma unroll
    for (int p = 0; p < 2; p++) {
        const uint32_t st = sb + p * STAGE_B;
        tile_async(AhB + p * BK, lda, st, tid);
        tile_async(AlB + p * BK, lda, st + TILE_B, tid);
        tile_async(BhB + p * BK, K, st + 2 * TILE_B, tid);
        tile_async(BlB + p * BK, K, st + 3 * TILE_B, tid);
        cp_commit();
    }

    for (int i = 0; i < NC; i++) {
        cp_wait1();
        __syncthreads();
        const int s = i & 1;
        const uint32_t* AsH = Su + s * (STAGE_B / 4);
        const uint32_t* AsL = AsH + TILE_B / 4;
        const uint32_t* BsH = AsH + 2 * (TILE_B / 4);
        const uint32_t* BsL = AsH + 3 * (TILE_B / 4);

#pragma unroll
        for (int ks = 0; ks < 2; ks++) {
            const int kc = ks * 8;   // u32 offset within row
            uint32_t ah[4][4], al[4][4];
#pragma unroll
            for (int mf = 0; mf < 4; mf++) {
                const int rb = (wm + mf * 16 + g) * TSTRIDE + kc + t;
                ah[mf][0] = AsH[rb];
                ah[mf][1] = AsH[rb + 8 * TSTRIDE];
                ah[mf][2] = AsH[rb + 4];
                ah[mf][3] = AsH[rb + 8 * TSTRIDE + 4];
                al[mf][0] = AsL[rb];
                al[mf][1] = AsL[rb + 8 * TSTRIDE];
                al[mf][2] = AsL[rb + 4];
                al[mf][3] = AsL[rb + 8 * TSTRIDE + 4];
            }
            uint32_t bh[8][2], bl[8][2];
#pragma unroll
            for (int nf = 0; nf < 8; nf++) {
                const int rb = (wn + nf * 8 + g) * TSTRIDE + kc + t;
                bh[nf][0] = BsH[rb];
                bh[nf][1] = BsH[rb + 4];
                bl[nf][0] = BsL[rb];
                bl[nf][1] = BsL[rb + 4];
            }
#pragma unroll
            for (int mf = 0; mf < 4; mf++)
#pragma unroll
                for (int nf = 0; nf < 8; nf++) {
                    mma_bf16(acc[mf][nf], ah[mf][0], ah[mf][1], ah[mf][2],
                             ah[mf][3], bh[nf][0], bh[nf][1]);
                    mma_bf16(acc[mf][nf], ah[mf][0], ah[mf][1], ah[mf][2],
                             ah[mf][3], bl[nf][0], bl[nf][1]);
                    mma_bf16(acc[mf][nf], al[mf][0], al[mf][1], al[mf][2],
                             al[mf][3], bh[nf][0], bh[nf][1]);
                }
        }
        __syncthreads();
        if (i + 2 < NC) {
            const int k0 = (i + 2) * BK;
            const uint32_t st = sb + s * STAGE_B;
            tile_async(AhB + k0, lda, st, tid);
            tile_async(AlB + k0, lda, st + TILE_B, tid);
            tile_async(BhB + k0, K, st + 2 * TILE_B, tid);
            tile_async(BlB + k0, K, st + 3 * TILE_B, tid);
        }
        cp_commit();
    }

    // Epilogue
    const bool hilo = (Ch != nullptr);
#pragma unroll
    for (int mf = 0; mf < 4; mf++) {
        const int row0 = m0 + wm + mf * 16 + g;
#pragma unroll
        for (int nf = 0; nf < 8; nf++) {
            const int col = n0 + wn + nf * 8 + 2 * t;
            const float b0 = bias[col], b1 = bias[col + 1];
            float v00 = acc[mf][nf][0] + b0, v01 = acc[mf][nf][1] + b1;
            float v10 = acc[mf][nf][2] + b0, v11 = acc[mf][nf][3] + b1;
            *(float2*)(C + (size_t)row0 * N + col) = make_float2(v00, v01);
            *(float2*)(C + (size_t)(row0 + 8) * N + col) = make_float2(v10, v11);
            if (hilo) {
                size_t o0 = (size_t)row0 * N + col;
                size_t o1 = (size_t)(row0 + 8) * N + col;
                __nv_bfloat16 h;
                h = __float2bfloat16_rn(v00); Ch[o0] = h;
                Cl[o0] = __float2bfloat16_rn(v00 - __bfloat162float(h));
                h = __float2bfloat16_rn(v01); Ch[o0 + 1] = h;
                Cl[o0 + 1] = __float2bfloat16_rn(v01 - __bfloat162float(h));
                h = __float2bfloat16_rn(v10); Ch[o1] = h;
                Cl[o1] = __float2bfloat16_rn(v10 - __bfloat162float(h));
                h = __float2bfloat16_rn(v11); Ch[o1 + 1] = h;
                Cl[o1 + 1] = __float2bfloat16_rn(v11 - __bfloat162float(h));
            }
        }
    }
}

// ---------------------------------------------------------------------------
// Elementwise fp32 -> bf16 hi/lo split (for h_t)
// ---------------------------------------------------------------------------
__global__ void split_kernel(const float* __restrict__ src,
                             __nv_bfloat16* __restrict__ hi,
                             __nv_bfloat16* __restrict__ lo, int n)
{
    int i = (blockIdx.x * 256 + threadIdx.x) * 4;
    if (i >= n) return;
    float4 v = *(const float4*)(src + i);
    __nv_bfloat16 h0 = __float2bfloat16_rn(v.x);
    __nv_bfloat16 h1 = __float2bfloat16_rn(v.y);
    __nv_bfloat16 h2 = __float2bfloat16_rn(v.z);
    __nv_bfloat16 h3 = __float2bfloat16_rn(v.w);
    __nv_bfloat16 l0 = __float2bfloat16_rn(v.x - __bfloat162float(h0));
    __nv_bfloat16 l1 = __float2bfloat16_rn(v.y - __bfloat162float(h1));
    __nv_bfloat16 l2 = __float2bfloat16_rn(v.z - __bfloat162float(h2));
    __nv_bfloat16 l3 = __float2bfloat16_rn(v.w - __bfloat162float(h3));
    *(__nv_bfloat162*)(hi + i)     = __nv_bfloat162(h0, h1);
    *(__nv_bfloat162*)(hi + i + 2) = __nv_bfloat162(h2, h3);
    *(__nv_bfloat162*)(lo + i)     = __nv_bfloat162(l0, l1);
    *(__nv_bfloat162*)(lo + i + 2) = __nv_bfloat162(l2, l3);
}

// ---------------------------------------------------------------------------
// Transpose + bf16 hi/lo split for weights: [rows,cols] fp32 -> [cols,rows]
// ---------------------------------------------------------------------------
__global__ void transpose_split(const float* __restrict__ src,
                                __nv_bfloat16* __restrict__ hi,
                                __nv_bfloat16* __restrict__ lo,
                                int rows, int cols)
{
    __shared__ float tile[32][33];
    const int c0 = blockIdx.x * 32, r0 = blockIdx.y * 32;
    for (int i = threadIdx.y; i < 32; i += 8)
        tile[i][threadIdx.x] = src[(size_t)(r0 + i) * cols + c0 + threadIdx.x];
    __syncthreads();
    for (int i = threadIdx.y; i < 32; i += 8) {
        float x = tile[threadIdx.x][i];
        __nv_bfloat16 h = __float2bfloat16_rn(x);
        __nv_bfloat16 l = __float2bfloat16_rn(x - __bfloat162float(h));
        size_t o = (size_t)(c0 + i) * rows + r0 + threadIdx.x;
        hi[o] = h;
        lo[o] = l;
    }
}

__global__ void copyf(const float* __restrict__ s, float* __restrict__ d, int n)
{
    int i = blockIdx.x * 256 + threadIdx.x;
    if (i < n) d[i] = s[i];
}

// ---------------------------------------------------------------------------
// Per-token attention (rope fused). 256 threads / token.
// Emits hi/lo bf16 output for G4.
// ---------------------------------------------------------------------------
#define QK_STRIDE 193

__global__ void __launch_bounds__(256) attn_kernel(
    const float* __restrict__ s1, const float* __restrict__ s2,
    const float* __restrict__ s3,
    __nv_bfloat16* __restrict__ obh, __nv_bfloat16* __restrict__ obl)
{
    const float SCALER = 1.0f / sqrtf((float)(DH + DRH));
    const float LOG1E4 = 9.210340371976184f;

    int tk = blockIdx.x;
    int s = tk & (SS - 1);
    int tid = threadIdx.x;

    __shared__ float qf[HH][QK_STRIDE];
    __shared__ float kf[HH][QK_STRIDE];
    __shared__ float vv[HH][DH];
    __shared__ float sc[HH][HH];
    __shared__ float at[HH][HH];

    const float* qp  = s2 + (size_t)tk * 3072;
    const float* qrp = qp + 2048;
    const float* kp  = s3 + (size_t)tk * 4096;
    const float* vp  = kp + 2048;
    const float* krp = s1 + (size_t)tk * 2048 + 1024;

    for (int idx = tid; idx < HH * DH; idx += 256) {
        int h = idx >> 7, d = idx & 127;
        qf[h][d] = qp[idx];
        kf[h][d] = kp[idx];
        vv[h][d] = vp[idx];
    }
    for (int idx = tid; idx < HH * 32; idx += 256) {
        int h = idx >> 5, j = idx & 31;
        float invf = expf(-LOG1E4 * ((float)(2 * j) / 64.0f));
        float ang = (float)s * invf;
        float sj, cj;
        sincosf(ang, &sj, &cj);
        float x1q = qrp[h * DRH + j], x2q = qrp[h * DRH + j + 32];
        qf[h][DH + j]      = x1q * cj - x2q * sj;
        qf[h][DH + j + 32] = x2q * cj + x1q * sj;
        float x1k = krp[h * DRH + j], x2k = krp[h * DRH + j + 32];
        kf[h][DH + j]      = x1k * cj - x2k * sj;
        kf[h][DH + j + 32] = x2k * cj + x1k * sj;
    }
    __syncthreads();

    {
        int i = tid >> 4, j = tid & 15;
        float dsum = 0.f;
#pragma unroll 8
        for (int d = 0; d < DH + DRH; d++)
            dsum = fmaf(qf[i][d], kf[j][d], dsum);
        sc[i][j] = dsum * SCALER;
    }
    __syncthreads();

    if (tid < HH) {
        float mx = -1e30f;
#pragma unroll
        for (int j = 0; j < HH; j++) mx = fmaxf(mx, sc[tid][j]);
        float e[HH], sum = 0.f;
#pragma unroll
        for (int j = 0; j < HH; j++) { e[j] = expf(sc[tid][j] - mx); sum += e[j]; }
        float inv = 1.0f / sum;
#pragma unroll
        for (int j = 0; j < HH; j++) at[tid][j] = e[j] * inv;
    }
    __syncthreads();

    for (int idx = tid; idx < HH * DH; idx += 256) {
        int i = idx >> 7, d = idx & 127;
        float acc = 0.f;
#pragma unroll
        for (int j = 0; j < HH; j++)
            acc = fmaf(at[i][j], vv[j][d], acc);
        size_t o = (size_t)tk * DKQV + idx;
        __nv_bfloat16 h = __float2bfloat16_rn(acc);
        obh[o] = h;
        obl[o] = __float2bfloat16_rn(acc - __bfloat162float(h));
    }
}

// ---------------------------------------------------------------------------
// Launch
// ---------------------------------------------------------------------------
static void launch_gemm(const __nv_bfloat16* Ah, const __nv_bfloat16* Al, int lda,
                        const __nv_bfloat16* Bh, const __nv_bfloat16* Bl,
                        const float* bias, float* C,
                        __nv_bfloat16* Ch, __nv_bfloat16* Cl,
                        int M, int N, int K)
{
    cudaFuncSetAttribute(gemm_bf16x3_kernel,
                         cudaFuncAttributeMaxDynamicSharedMemorySize, SMEM_BYTES);
    dim3 grid(N / BN, M / BM);
    gemm_bf16x3_kernel<<<grid, 128, SMEM_BYTES>>>(Ah, Al, lda, Bh, Bl, bias, C,
                                                  Ch, Cl, M, N, K);
}

static void launch_tsplit(const float* src, __nv_bfloat16* hi, __nv_bfloat16* lo,
                          int rows, int cols)
{
    dim3 grid(cols / 32, rows / 32), blk(32, 8);
    transpose_split<<<grid, blk>>>(src, hi, lo, rows, cols);
}

static void launch_copy(const float* s, float* d, int n)
{
    copyf<<<(n + 255) / 256, 256>>>(s, d, n);
}

extern "C" void kernel_launch(void* const* d_in, const int* in_sizes, int n_in,
                              void* d_out, int out_size)
{
    const float* h_t  = (const float*)d_in[0];
    const float* Wc   = (const float*)d_in[1];
    const float* bc   = (const float*)d_in[2];
    const float* Wcq  = (const float*)d_in[3];
    const float* bcq  = (const float*)d_in[4];
    const float* Wqr  = (const float*)d_in[5];
    const float* bqr  = (const float*)d_in[6];
    const float* Wckv = (const float*)d_in[7];
    const float* bckv = (const float*)d_in[8];
    const float* Wck  = (const float*)d_in[9];
    const float* bck  = (const float*)d_in[10];
    const float* Wkr  = (const float*)d_in[11];
    const float* bkr  = (const float*)d_in[12];
    const float* Wv   = (const float*)d_in[13];
    const float* bv   = (const float*)d_in[14];
    const float* Wo   = (const float*)d_in[15];
    const float* bo   = (const float*)d_in[16];
    float* out = (float*)d_out;

    float *s1, *s2, *s3, *b1, *b2, *b3;
    __nv_bfloat16 *s1h, *s1l, *hth, *htl, *obh, *obl;
    __nv_bfloat16 *w1h, *w1l, *w2h, *w2l, *w3h, *w3l, *w4h, *w4l;
    cudaGetSymbolAddress((void**)&s1,  g_s1);
    cudaGetSymbolAddress((void**)&s1h, g_s1h);
    cudaGetSymbolAddress((void**)&s1l, g_s1l);
    cudaGetSymbolAddress((void**)&s2,  g_s2);
    cudaGetSymbolAddress((void**)&s3,  g_s3);
    cudaGetSymbolAddress((void**)&hth, g_hth);
    cudaGetSymbolAddress((void**)&htl, g_htl);
    cudaGetSymbolAddress((void**)&obh, g_obh);
    cudaGetSymbolAddress((void**)&obl, g_obl);
    cudaGetSymbolAddress((void**)&w1h, g_w1h);
    cudaGetSymbolAddress((void**)&w1l, g_w1l);
    cudaGetSymbolAddress((void**)&w2h, g_w2h);
    cudaGetSymbolAddress((void**)&w2l, g_w2l);
    cudaGetSymbolAddress((void**)&w3h, g_w3h);
    cudaGetSymbolAddress((void**)&w3l, g_w3l);
    cudaGetSymbolAddress((void**)&w4h, g_w4h);
    cudaGetSymbolAddress((void**)&w4l, g_w4l);
    cudaGetSymbolAddress((void**)&b1,  g_b1);
    cudaGetSymbolAddress((void**)&b2,  g_b2);
    cudaGetSymbolAddress((void**)&b3,  g_b3);

    // Pack: weights (transpose + split) and h_t (split)
    launch_tsplit(Wc,   w1h + (size_t)0    * 2048, w1l + (size_t)0    * 2048, 2048, 512);
    launch_tsplit(Wckv, w1h + (size_t)512  * 2048, w1l + (size_t)512  * 2048, 2048, 512);
    launch_tsplit(Wkr,  w1h + (size_t)1024 * 2048, w1l + (size_t)1024 * 2048, 2048, 1024);
    launch_tsplit(Wcq,  w2h + (size_t)0    * 512,  w2l + (size_t)0    * 512,  512, 2048);
    launch_tsplit(Wqr,  w2h + (size_t)2048 * 512,  w2l + (size_t)2048 * 512,  512, 1024);
    launch_tsplit(Wck,  w3h + (size_t)0    * 512,  w3l + (size_t)0    * 512,  512, 2048);
    launch_tsplit(Wv,   w3h + (size_t)2048 * 512,  w3l + (size_t)2048 * 512,  512, 2048);
    launch_tsplit(Wo,   w4h, w4l, 2048, 2048);
    launch_copy(bc,   b1,        512);
    launch_copy(bckv, b1 + 512,  512);
    launch_copy(bkr,  b1 + 1024, 1024);
    launch_copy(bcq,  b2,        2048);
    launch_copy(bqr,  b2 + 2048, 1024);
    launch_copy(bck,  b3,        2048);
    launch_copy(bv,   b3 + 2048, 2048);
    {
        int n = MTOK * 2048;
        split_kernel<<<(n / 4 + 255) / 256, 256>>>(h_t, hth, htl, n);
    }

    // G1: h_t -> (cq|ckv|kr), fp32 + hi/lo
    launch_gemm(hth, htl, 2048, w1h, w1l, b1, s1, s1h, s1l, MTOK, 2048, 2048);
    // G2: cq -> (q|qr), fp32 only
    launch_gemm(s1h, s1l, 2048, w2h, w2l, b2, s2, nullptr, nullptr, MTOK, 3072, 512);
    // G3: ckv -> (k|v), fp32 only
    launch_gemm(s1h + 512, s1l + 512, 2048, w3h, w3l, b3, s3, nullptr, nullptr,
                MTOK, 4096, 512);
    // attention -> hi/lo bf16
    attn_kernel<<<MTOK, 256>>>(s1, s2, s3, obh, obl);
    // G4: o -> out
    launch_gemm(obh, obl, 2048, w4h, w4l, bo, out, nullptr, nullptr, MTOK, 2048, 2048);
}

// round 9
// speedup vs baseline: 1.1345x; 1.0395x over previous
#include <cuda_runtime.h>
#include <cuda_bf16.h>
#include <math.h>
#include <stdint.h>

// ---------------------------------------------------------------------------
// Problem constants
// ---------------------------------------------------------------------------
#define BB 2
#define SS 4096
#define HH 16
#define DKQV 2048
#define DH 128
#define DRH 64
#define MTOK (BB*SS)            // 8192 tokens

// ---------------------------------------------------------------------------
// Device scratch
// ---------------------------------------------------------------------------
__device__ float g_s1 [MTOK * 2048];                       // cq | ckv | kr (fp32)
__device__ __nv_bfloat16 g_s1h[MTOK * 2048], g_s1l[MTOK * 2048];
__device__ float g_s2 [MTOK * 3072];                       // q | qr
__device__ float g_s3 [MTOK * 4096];                       // k | v
__device__ __nv_bfloat16 g_hth[MTOK * 2048], g_htl[MTOK * 2048];  // h_t split
__device__ __nv_bfloat16 g_obh[MTOK * 2048], g_obl[MTOK * 2048];  // attn out split
__device__ __nv_bfloat16 g_w1h[2048 * 2048], g_w1l[2048 * 2048];
__device__ __nv_bfloat16 g_w2h[3072 * 512],  g_w2l[3072 * 512];
__device__ __nv_bfloat16 g_w3h[4096 * 512],  g_w3l[4096 * 512];
__device__ __nv_bfloat16 g_w4h[2048 * 2048], g_w4l[2048 * 2048];
__device__ float g_b1 [2048];
__device__ float g_b2 [3072];
__device__ float g_b3 [4096];

// ---------------------------------------------------------------------------
// GEMM config: CTA 128x128, BK=32, 128 threads (4 warps of 64x64), 2 stages
// bf16 tiles [128 rows][32 k] in smem, row stride 20 u32 (16 data + 4 pad).
// stride 20: (r*20 mod 32)/4 permutes the eight 4-bank groups -> every
// ldmatrix 8-row phase is conflict-free.
// ---------------------------------------------------------------------------
#define BM 128
#define BN 128
#define BK 32
#define TSTRIDE 20
#define TILE_B (128 * TSTRIDE * 4)      // 10240 bytes
#define STAGE_B (4 * TILE_B)            // Ah, Al, Bh, Bl = 40960
#define SMEM_BYTES (2 * STAGE_B)        // 81920 -> 2 CTAs/SM

__device__ __forceinline__ uint32_t smem_u32(const void* p) {
    uint32_t a;
    asm("{ .reg .u64 t; cvta.to.shared.u64 t, %1; cvt.u32.u64 %0, t; }"
        : "=r"(a) : "l"(p));
    return a;
}
__device__ __forceinline__ void cp_async16(uint32_t dst, const void* src) {
    asm volatile("cp.async.cg.shared.global [%0], [%1], 16;"
                 :: "r"(dst), "l"(src) : "memory");
}
__device__ __forceinline__ void cp_commit() {
    asm volatile("cp.async.commit_group;" ::: "memory");
}
__device__ __forceinline__ void cp_wait1() {
    asm volatile("cp.async.wait_group 1;" ::: "memory");
}

__device__ __forceinline__ void mma_bf16(float c[4], uint32_t a0, uint32_t a1,
                                         uint32_t a2, uint32_t a3,
                                         uint32_t b0, uint32_t b1) {
    asm volatile(
        "mma.sync.aligned.m16n8k16.row.col.f32.bf16.bf16.f32 "
        "{%0,%1,%2,%3}, {%4,%5,%6,%7}, {%8,%9}, {%0,%1,%2,%3};"
        : "+f"(c[0]), "+f"(c[1]), "+f"(c[2]), "+f"(c[3])
        : "r"(a0), "r"(a1), "r"(a2), "r"(a3), "r"(b0), "r"(b1));
}

__device__ __forceinline__ void ldsm_x4(uint32_t& r0, uint32_t& r1,
                                        uint32_t& r2, uint32_t& r3,
                                        uint32_t addr) {
    asm volatile("ldmatrix.sync.aligned.m8n8.x4.shared.b16 {%0,%1,%2,%3}, [%4];"
                 : "=r"(r0), "=r"(r1), "=r"(r2), "=r"(r3) : "r"(addr));
}

// bf16 [row,K] tile (128 rows x 32 cols = 64B/row) -> smem [128][20 u32]
__device__ __forceinline__ void tile_async(const __nv_bfloat16* __restrict__ g,
                                           int ld, uint32_t sbase, int tid) {
#pragma unroll
    for (int j = 0; j < 4; j++) {
        int idx = tid + j * 128;       // 0..511
        int r = idx >> 2, c = idx & 3; // 4 x 16B chunks per row
        cp_async16(sbase + (uint32_t)(r * TSTRIDE + c * 4) * 4,
                   g + (size_t)r * ld + c * 8);
    }
}

// ---------------------------------------------------------------------------
// bf16x3 GEMM: C = (Ah+Al)[M,K] @ (Bh+Bl)[N,K]^T + bias
// Optionally also emits hi/lo bf16 copies of C. grid(N/128, M/128), 128 thr.
// ---------------------------------------------------------------------------
__global__ void __launch_bounds__(128, 2) gemm_bf16x3_kernel(
    const __nv_bfloat16* __restrict__ Ah,
    const __nv_bfloat16* __restrict__ Al, int lda,
    const __nv_bfloat16* __restrict__ Bh,
    const __nv_bfloat16* __restrict__ Bl,
    const float* __restrict__ bias,
    float* __restrict__ C,
    __nv_bfloat16* __restrict__ Ch,       // may be null
    __nv_bfloat16* __restrict__ Cl,
    int M, int N, int K)
{
    extern __shared__ float smem[];
    const uint32_t sb = smem_u32(smem);
    const int tid = threadIdx.x;
    const int wid = tid >> 5;
    const int lane = tid & 31;
    const int g = lane >> 2;
    const int t = lane & 3;
    const int wm = (wid & 1) * 64;
    const int wn = (wid >> 1) * 64;

    // ldmatrix per-lane address components
    const int lrow = lane & 7;        // row within 8x8 matrix
    const int lsel = lane >> 3;       // matrix id 0..3
    // A x4: mats = (r0-7,k0-7),(r8-15,k0-7),(r0-7,k8-15),(r8-15,k8-15)
    const int a_row = wm + (lsel & 1) * 8 + lrow;
    const int a_col = (lsel >> 1) * 4;            // u32 offset
    // B x4 over nf pair: mats = (n0-7,k0-7),(n0-7,k8-15),(n8-15,k0-7),(n8-15,k8-15)
    const int b_row = wn + (lsel >> 1) * 8 + lrow;
    const int b_col = (lsel & 1) * 4;

    const int m0 = blockIdx.y * BM;
    const int n0 = blockIdx.x * BN;
    const __nv_bfloat16* AhB = Ah + (size_t)m0 * lda;
    const __nv_bfloat16* AlB = Al + (size_t)m0 * lda;
    const __nv_bfloat16* BhB = Bh + (size_t)n0 * K;
    const __nv_bfloat16* BlB = Bl + (size_t)n0 * K;

    float acc[4][8][4];
#pragma unroll
    for (int mf = 0; mf < 4; mf++)
#pragma unroll
        for (int nf = 0; nf < 8; nf++)
#pragma unroll
            for (int r = 0; r < 4; r++) acc[mf][nf][r] = 0.f;

    const int NC = K / BK;

#pragma unroll
    for (int p = 0; p < 2; p++) {
        const uint32_t st = sb + p * STAGE_B;
        tile_async(AhB + p * BK, lda, st, tid);
        tile_async(AlB + p * BK, lda, st + TILE_B, tid);
        tile_async(BhB + p * BK, K, st + 2 * TILE_B, tid);
        tile_async(BlB + p * BK, K, st + 3 * TILE_B, tid);
        cp_commit();
    }

    for (int i = 0; i < NC; i++) {
        cp_wait1();
        __syncthreads();
        const int s = i & 1;
        const uint32_t stAh = sb + s * STAGE_B;
        const uint32_t stAl = stAh + TILE_B;
        const uint32_t stBh = stAh + 2 * TILE_B;
        const uint32_t stBl = stAh + 3 * TILE_B;
        const uint32_t aoff = (uint32_t)(a_row * TSTRIDE + a_col) * 4;
        const uint32_t boff = (uint32_t)(b_row * TSTRIDE + b_col) * 4;

#pragma unroll
        for (int ks = 0; ks < 2; ks++) {
            const uint32_t kb = (uint32_t)(ks * 8) * 4;   // byte offset in row
            uint32_t ah[4][4], al[4][4], bh[8][2], bl[8][2];
#pragma unroll
            for (int mf = 0; mf < 4; mf++) {
                const uint32_t ao = (uint32_t)(mf * 16 * TSTRIDE) * 4 + kb;
                ldsm_x4(ah[mf][0], ah[mf][1], ah[mf][2], ah[mf][3],
                        stAh + aoff + ao);
                ldsm_x4(al[mf][0], al[mf][1], al[mf][2], al[mf][3],
                        stAl + aoff + ao);
            }
#pragma unroll
            for (int p = 0; p < 4; p++) {                  // nf pairs
                const uint32_t bo = (uint32_t)(p * 16 * TSTRIDE) * 4 + kb;
                ldsm_x4(bh[2*p][0], bh[2*p][1], bh[2*p+1][0], bh[2*p+1][1],
                        stBh + boff + bo);
                ldsm_x4(bl[2*p][0], bl[2*p][1], bl[2*p+1][0], bl[2*p+1][1],
                        stBl + boff + bo);
            }
#pragma unroll
            for (int mf = 0; mf < 4; mf++)
#pragma unroll
                for (int nf = 0; nf < 8; nf++) {
                    mma_bf16(acc[mf][nf], ah[mf][0], ah[mf][1], ah[mf][2],
                             ah[mf][3], bh[nf][0], bh[nf][1]);
                    mma_bf16(acc[mf][nf], ah[mf][0], ah[mf][1], ah[mf][2],
                             ah[mf][3], bl[nf][0], bl[nf][1]);
                    mma_bf16(acc[mf][nf], al[mf][0], al[mf][1], al[mf][2],
                             al[mf][3], bh[nf][0], bh[nf][1]);
                }
        }
        __syncthreads();
        if (i + 2 < NC) {
            const int k0 = (i + 2) * BK;
            const uint32_t st = sb + s * STAGE_B;
            tile_async(AhB + k0, lda, st, tid);
            tile_async(AlB + k0, lda, st + TILE_B, tid);
            tile_async(BhB + k0, K, st + 2 * TILE_B, tid);
            tile_async(BlB + k0, K, st + 3 * TILE_B, tid);
        }
        cp_commit();
    }

    // Epilogue
    const bool hilo = (Ch != nullptr);
#pragma unroll
    for (int mf = 0; mf < 4; mf++) {
        const int row0 = m0 + wm + mf * 16 + g;
#pragma unroll
        for (int nf = 0; nf < 8; nf++) {
            const int col = n0 + wn + nf * 8 + 2 * t;
            const float b0 = bias[col], b1 = bias[col + 1];
            float v00 = acc[mf][nf][0] + b0, v01 = acc[mf][nf][1] + b1;
            float v10 = acc[mf][nf][2] + b0, v11 = acc[mf][nf][3] + b1;
            *(float2*)(C + (size_t)row0 * N + col) = make_float2(v00, v01);
            *(float2*)(C + (size_t)(row0 + 8) * N + col) = make_float2(v10, v11);
            if (hilo) {
                size_t o0 = (size_t)row0 * N + col;
                size_t o1 = (size_t)(row0 + 8) * N + col;
                __nv_bfloat16 h;
                h = __float2bfloat16_rn(v00); Ch[o0] = h;
                Cl[o0] = __float2bfloat16_rn(v00 - __bfloat162float(h));
                h = __float2bfloat16_rn(v01); Ch[o0 + 1] = h;
                Cl[o0 + 1] = __float2bfloat16_rn(v01 - __bfloat162float(h));
                h = __float2bfloat16_rn(v10); Ch[o1] = h;
                Cl[o1] = __float2bfloat16_rn(v10 - __bfloat162float(h));
                h = __float2bfloat16_rn(v11); Ch[o1 + 1] = h;
                Cl[o1 + 1] = __float2bfloat16_rn(v11 - __bfloat162float(h));
            }
        }
    }
}

// ---------------------------------------------------------------------------
// Elementwise fp32 -> bf16 hi/lo split (for h_t)
// ---------------------------------------------------------------------------
__global__ void split_kernel(const float* __restrict__ src,
                             __nv_bfloat16* __restrict__ hi,
                             __nv_bfloat16* __restrict__ lo, int n)
{
    int i = (blockIdx.x * 256 + threadIdx.x) * 4;
    if (i >= n) return;
    float4 v = *(const float4*)(src + i);
    __nv_bfloat16 h0 = __float2bfloat16_rn(v.x);
    __nv_bfloat16 h1 = __float2bfloat16_rn(v.y);
    __nv_bfloat16 h2 = __float2bfloat16_rn(v.z);
    __nv_bfloat16 h3 = __float2bfloat16_rn(v.w);
    __nv_bfloat16 l0 = __float2bfloat16_rn(v.x - __bfloat162float(h0));
    __nv_bfloat16 l1 = __float2bfloat16_rn(v.y - __bfloat162float(h1));
    __nv_bfloat16 l2 = __float2bfloat16_rn(v.z - __bfloat162float(h2));
    __nv_bfloat16 l3 = __float2bfloat16_rn(v.w - __bfloat162float(h3));
    *(__nv_bfloat162*)(hi + i)     = __nv_bfloat162(h0, h1);
    *(__nv_bfloat162*)(hi + i + 2) = __nv_bfloat162(h2, h3);
    *(__nv_bfloat162*)(lo + i)     = __nv_bfloat162(l0, l1);
    *(__nv_bfloat162*)(lo + i + 2) = __nv_bfloat162(l2, l3);
}

// ---------------------------------------------------------------------------
// Transpose + bf16 hi/lo split for weights: [rows,cols] fp32 -> [cols,rows]
// ---------------------------------------------------------------------------
__global__ void transpose_split(const float* __restrict__ src,
                                __nv_bfloat16* __restrict__ hi,
                                __nv_bfloat16* __restrict__ lo,
                                int rows, int cols)
{
    __shared__ float tile[32][33];
    const int c0 = blockIdx.x * 32, r0 = blockIdx.y * 32;
    for (int i = threadIdx.y; i < 32; i += 8)
        tile[i][threadIdx.x] = src[(size_t)(r0 + i) * cols + c0 + threadIdx.x];
    __syncthreads();
    for (int i = threadIdx.y; i < 32; i += 8) {
        float x = tile[threadIdx.x][i];
        __nv_bfloat16 h = __float2bfloat16_rn(x);
        __nv_bfloat16 l = __float2bfloat16_rn(x - __bfloat162float(h));
        size_t o = (size_t)(c0 + i) * rows + r0 + threadIdx.x;
        hi[o] = h;
        lo[o] = l;
    }
}

__global__ void copyf(const float* __restrict__ s, float* __restrict__ d, int n)
{
    int i = blockIdx.x * 256 + threadIdx.x;
    if (i < n) d[i] = s[i];
}

// ---------------------------------------------------------------------------
// Per-token attention (rope fused). 256 threads / token.
// ---------------------------------------------------------------------------
#define QK_STRIDE 193

__global__ void __launch_bounds__(256) attn_kernel(
    const float* __restrict__ s1, const float* __restrict__ s2,
    const float* __restrict__ s3,
    __nv_bfloat16* __restrict__ obh, __nv_bfloat16* __restrict__ obl)
{
    const float SCALER = 1.0f / sqrtf((float)(DH + DRH));
    const float LOG1E4 = 9.210340371976184f;

    int tk = blockIdx.x;
    int s = tk & (SS - 1);
    int tid = threadIdx.x;

    __shared__ float qf[HH][QK_STRIDE];
    __shared__ float kf[HH][QK_STRIDE];
    __shared__ float vv[HH][DH];
    __shared__ float sc[HH][HH];
    __shared__ float at[HH][HH];

    const float* qp  = s2 + (size_t)tk * 3072;
    const float* qrp = qp + 2048;
    const float* kp  = s3 + (size_t)tk * 4096;
    const float* vp  = kp + 2048;
    const float* krp = s1 + (size_t)tk * 2048 + 1024;

    for (int idx = tid; idx < HH * DH; idx += 256) {
        int h = idx >> 7, d = idx & 127;
        qf[h][d] = qp[idx];
        kf[h][d] = kp[idx];
        vv[h][d] = vp[idx];
    }
    for (int idx = tid; idx < HH * 32; idx += 256) {
        int h = idx >> 5, j = idx & 31;
        float invf = expf(-LOG1E4 * ((float)(2 * j) / 64.0f));
        float ang = (float)s * invf;
        float sj, cj;
        sincosf(ang, &sj, &cj);
        float x1q = qrp[h * DRH + j], x2q = qrp[h * DRH + j + 32];
        qf[h][DH + j]      = x1q * cj - x2q * sj;
        qf[h][DH + j + 32] = x2q * cj + x1q * sj;
        float x1k = krp[h * DRH + j], x2k = krp[h * DRH + j + 32];
        kf[h][DH + j]      = x1k * cj - x2k * sj;
        kf[h][DH + j + 32] = x2k * cj + x1k * sj;
    }
    __syncthreads();

    {
        int i = tid >> 4, j = tid & 15;
        float dsum = 0.f;
#pragma unroll 8
        for (int d = 0; d < DH + DRH; d++)
            dsum = fmaf(qf[i][d], kf[j][d], dsum);
        sc[i][j] = dsum * SCALER;
    }
    __syncthreads();

    if (tid < HH) {
        float mx = -1e30f;
#pragma unroll
        for (int j = 0; j < HH; j++) mx = fmaxf(mx, sc[tid][j]);
        float e[HH], sum = 0.f;
#pragma unroll
        for (int j = 0; j < HH; j++) { e[j] = expf(sc[tid][j] - mx); sum += e[j]; }
        float inv = 1.0f / sum;
#pragma unroll
        for (int j = 0; j < HH; j++) at[tid][j] = e[j] * inv;
    }
    __syncthreads();

    for (int idx = tid; idx < HH * DH; idx += 256) {
        int i = idx >> 7, d = idx & 127;
        float acc = 0.f;
#pragma unroll
        for (int j = 0; j < HH; j++)
            acc = fmaf(at[i][j], vv[j][d], acc);
        size_t o = (size_t)tk * DKQV + idx;
        __nv_bfloat16 h = __float2bfloat16_rn(acc);
        obh[o] = h;
        obl[o] = __float2bfloat16_rn(acc - __bfloat162float(h));
    }
}

// ---------------------------------------------------------------------------
// Launch
// ---------------------------------------------------------------------------
static void launch_gemm(const __nv_bfloat16* Ah, const __nv_bfloat16* Al, int lda,
                        const __nv_bfloat16* Bh, const __nv_bfloat16* Bl,
                        const float* bias, float* C,
                        __nv_bfloat16* Ch, __nv_bfloat16* Cl,
                        int M, int N, int K)
{
    cudaFuncSetAttribute(gemm_bf16x3_kernel,
                         cudaFuncAttributeMaxDynamicSharedMemorySize, SMEM_BYTES);
    dim3 grid(N / BN, M / BM);
    gemm_bf16x3_kernel<<<grid, 128, SMEM_BYTES>>>(Ah, Al, lda, Bh, Bl, bias, C,
                                                  Ch, Cl, M, N, K);
}

static void launch_tsplit(const float* src, __nv_bfloat16* hi, __nv_bfloat16* lo,
                          int rows, int cols)
{
    dim3 grid(cols / 32, rows / 32), blk(32, 8);
    transpose_split<<<grid, blk>>>(src, hi, lo, rows, cols);
}

static void launch_copy(const float* s, float* d, int n)
{
    copyf<<<(n + 255) / 256, 256>>>(s, d, n);
}

extern "C" void kernel_launch(void* const* d_in, const int* in_sizes, int n_in,
                              void* d_out, int out_size)
{
    const float* h_t  = (const float*)d_in[0];
    const float* Wc   = (const float*)d_in[1];
    const float* bc   = (const float*)d_in[2];
    const float* Wcq  = (const float*)d_in[3];
    const float* bcq  = (const float*)d_in[4];
    const float* Wqr  = (const float*)d_in[5];
    const float* bqr  = (const float*)d_in[6];
    const float* Wckv = (const float*)d_in[7];
    const float* bckv = (const float*)d_in[8];
    const float* Wck  = (const float*)d_in[9];
    const float* bck  = (const float*)d_in[10];
    const float* Wkr  = (const float*)d_in[11];
    const float* bkr  = (const float*)d_in[12];
    const float* Wv   = (const float*)d_in[13];
    const float* bv   = (const float*)d_in[14];
    const float* Wo   = (const float*)d_in[15];
    const float* bo   = (const float*)d_in[16];
    float* out = (float*)d_out;

    float *s1, *s2, *s3, *b1, *b2, *b3;
    __nv_bfloat16 *s1h, *s1l, *hth, *htl, *obh, *obl;
    __nv_bfloat16 *w1h, *w1l, *w2h, *w2l, *w3h, *w3l, *w4h, *w4l;
    cudaGetSymbolAddress((void**)&s1,  g_s1);
    cudaGetSymbolAddress((void**)&s1h, g_s1h);
    cudaGetSymbolAddress((void**)&s1l, g_s1l);
    cudaGetSymbolAddress((void**)&s2,  g_s2);
    cudaGetSymbolAddress((void**)&s3,  g_s3);
    cudaGetSymbolAddress((void**)&hth, g_hth);
    cudaGetSymbolAddress((void**)&htl, g_htl);
    cudaGetSymbolAddress((void**)&obh, g_obh);
    cudaGetSymbolAddress((void**)&obl, g_obl);
    cudaGetSymbolAddress((void**)&w1h, g_w1h);
    cudaGetSymbolAddress((void**)&w1l, g_w1l);
    cudaGetSymbolAddress((void**)&w2h, g_w2h);
    cudaGetSymbolAddress((void**)&w2l, g_w2l);
    cudaGetSymbolAddress((void**)&w3h, g_w3h);
    cudaGetSymbolAddress((void**)&w3l, g_w3l);
    cudaGetSymbolAddress((void**)&w4h, g_w4h);
    cudaGetSymbolAddress((void**)&w4l, g_w4l);
    cudaGetSymbolAddress((void**)&b1,  g_b1);
    cudaGetSymbolAddress((void**)&b2,  g_b2);
    cudaGetSymbolAddress((void**)&b3,  g_b3);

    // Pack: weights (transpose + split) and h_t (split)
    launch_tsplit(Wc,   w1h + (size_t)0    * 2048, w1l + (size_t)0    * 2048, 2048, 512);
    launch_tsplit(Wckv, w1h + (size_t)512  * 2048, w1l + (size_t)512  * 2048, 2048, 512);
    launch_tsplit(Wkr,  w1h + (size_t)1024 * 2048, w1l + (size_t)1024 * 2048, 2048, 1024);
    launch_tsplit(Wcq,  w2h + (size_t)0    * 512,  w2l + (size_t)0    * 512,  512, 2048);
    launch_tsplit(Wqr,  w2h + (size_t)2048 * 512,  w2l + (size_t)2048 * 512,  512, 1024);
    launch_tsplit(Wck,  w3h + (size_t)0    * 512,  w3l + (size_t)0    * 512,  512, 2048);
    launch_tsplit(Wv,   w3h + (size_t)2048 * 512,  w3l + (size_t)2048 * 512,  512, 2048);
    launch_tsplit(Wo,   w4h, w4l, 2048, 2048);
    launch_copy(bc,   b1,        512);
    launch_copy(bckv, b1 + 512,  512);
    launch_copy(bkr,  b1 + 1024, 1024);
    launch_copy(bcq,  b2,        2048);
    launch_copy(bqr,  b2 + 2048, 1024);
    launch_copy(bck,  b3,        2048);
    launch_copy(bv,   b3 + 2048, 2048);
    {
        int n = MTOK * 2048;
        split_kernel<<<(n / 4 + 255) / 256, 256>>>(h_t, hth, htl, n);
    }

    // G1: h_t -> (cq|ckv|kr), fp32 + hi/lo
    launch_gemm(hth, htl, 2048, w1h, w1l, b1, s1, s1h, s1l, MTOK, 2048, 2048);
    // G2: cq -> (q|qr)
    launch_gemm(s1h, s1l, 2048, w2h, w2l, b2, s2, nullptr, nullptr, MTOK, 3072, 512);
    // G3: ckv -> (k|v)
    launch_gemm(s1h + 512, s1l + 512, 2048, w3h, w3l, b3, s3, nullptr, nullptr,
                MTOK, 4096, 512);
    // attention -> hi/lo bf16
    attn_kernel<<<MTOK, 256>>>(s1, s2, s3, obh, obl);
    // G4: o -> out
    launch_gemm(obh, obl, 2048, w4h, w4l, bo, out, nullptr, nullptr, MTOK, 2048, 2048);
}

// round 14
// speedup vs baseline: 1.4913x; 1.3145x over previous
#include <cuda_runtime.h>
#include <cuda_fp16.h>
#include <math.h>
#include <stdint.h>

// ---------------------------------------------------------------------------
// Problem constants
// ---------------------------------------------------------------------------
#define BB 2
#define SS 4096
#define HH 16
#define DKQV 2048
#define DH 128
#define DRH 64
#define MTOK (BB*SS)            // 8192 tokens

// ---------------------------------------------------------------------------
// Device scratch
// ---------------------------------------------------------------------------
__device__ float g_s1 [MTOK * 2048];                       // cq | ckv | kr (fp32)
__device__ __half g_s1h[MTOK * 2048], g_s1l[MTOK * 2048];
__device__ float g_s2 [MTOK * 3072];                       // q | qr
__device__ float g_s3 [MTOK * 4096];                       // k | v
__device__ __half g_hth[MTOK * 2048], g_htl[MTOK * 2048];  // h_t split
__device__ __half g_obh[MTOK * 2048], g_obl[MTOK * 2048];  // attn out split
__device__ __half g_w1[2048 * 2048];                       // (Wc|Wckv|Wkr)^T fp16
__device__ __half g_w2[3072 * 512];                        // (Wcq|Wqr)^T
__device__ __half g_w3[4096 * 512];                        // (Wck|Wv)^T
__device__ __half g_w4[2048 * 2048];                       // Wo^T
__device__ float g_b1 [2048];
__device__ float g_b2 [3072];
__device__ float g_b3 [4096];

// ---------------------------------------------------------------------------
// GEMM config: CTA 128x128, BK=32, 128 threads (4 warps of 64x64), 2 stages
// fp16 tiles [128 rows][32 k] in smem, row stride 20 u32 (16 data + 4 pad).
// stride 20: (r*20 mod 32)/4 permutes the eight 4-bank groups -> every
// ldmatrix 8-row phase is conflict-free.
// ---------------------------------------------------------------------------
#define BM 128
#define BN 128
#define BK 32
#define TSTRIDE 20
#define TILE_B (128 * TSTRIDE * 4)      // 10240 bytes
#define STAGE_B (3 * TILE_B)            // Ah, Al, B = 30720
#define SMEM_BYTES (2 * STAGE_B)        // 61440 -> 2 CTAs/SM

__device__ __forceinline__ uint32_t smem_u32(const void* p) {
    uint32_t a;
    asm("{ .reg .u64 t; cvta.to.shared.u64 t, %1; cvt.u32.u64 %0, t; }"
        : "=r"(a) : "l"(p));
    return a;
}
__device__ __forceinline__ void cp_async16(uint32_t dst, const void* src) {
    asm volatile("cp.async.cg.shared.global [%0], [%1], 16;"
                 :: "r"(dst), "l"(src) : "memory");
}
__device__ __forceinline__ void cp_commit() {
    asm volatile("cp.async.commit_group;" ::: "memory");
}
__device__ __forceinline__ void cp_wait1() {
    asm volatile("cp.async.wait_group 1;" ::: "memory");
}

__device__ __forceinline__ void mma_fp16(float c[4], uint32_t a0, uint32_t a1,
                                         uint32_t a2, uint32_t a3,
                                         uint32_t b0, uint32_t b1) {
    asm volatile(
        "mma.sync.aligned.m16n8k16.row.col.f32.f16.f16.f32 "
        "{%0,%1,%2,%3}, {%4,%5,%6,%7}, {%8,%9}, {%0,%1,%2,%3};"
        : "+f"(c[0]), "+f"(c[1]), "+f"(c[2]), "+f"(c[3])
        : "r"(a0), "r"(a1), "r"(a2), "r"(a3), "r"(b0), "r"(b1));
}

__device__ __forceinline__ void ldsm_x4(uint32_t& r0, uint32_t& r1,
                                        uint32_t& r2, uint32_t& r3,
                                        uint32_t addr) {
    asm volatile("ldmatrix.sync.aligned.m8n8.x4.shared.b16 {%0,%1,%2,%3}, [%4];"
                 : "=r"(r0), "=r"(r1), "=r"(r2), "=r"(r3) : "r"(addr));
}

// fp16 [row,K] tile (128 rows x 32 cols = 64B/row) -> smem [128][20 u32]
__device__ __forceinline__ void tile_async(const __half* __restrict__ g,
                                           int ld, uint32_t sbase, int tid) {
#pragma unroll
    for (int j = 0; j < 4; j++) {
        int idx = tid + j * 128;       // 0..511
        int r = idx >> 2, c = idx & 3; // 4 x 16B chunks per row
        cp_async16(sbase + (uint32_t)(r * TSTRIDE + c * 4) * 4,
                   g + (size_t)r * ld + c * 8);
    }
}

// ---------------------------------------------------------------------------
// fp16x2 GEMM: C = (Ah+Al)[M,K] @ B[N,K]^T + bias, fp32 accumulate.
// Optionally also emits hi/lo fp16 copies of C. grid(N/128, M/128), 128 thr.
// ---------------------------------------------------------------------------
__global__ void __launch_bounds__(128, 2) gemm_fp16x2_kernel(
    const __half* __restrict__ Ah,
    const __half* __restrict__ Al, int lda,
    const __half* __restrict__ Bw,
    const float* __restrict__ bias,
    float* __restrict__ C,
    __half* __restrict__ Ch,       // may be null
    __half* __restrict__ Cl,
    int M, int N, int K)
{
    extern __shared__ float smem[];
    const uint32_t sb = smem_u32(smem);
    const int tid = threadIdx.x;
    const int wid = tid >> 5;
    const int lane = tid & 31;
    const int g = lane >> 2;
    const int t = lane & 3;
    const int wm = (wid & 1) * 64;
    const int wn = (wid >> 1) * 64;

    // ldmatrix per-lane address components
    const int lrow = lane & 7;        // row within 8x8 matrix
    const int lsel = lane >> 3;       // matrix id 0..3
    const int a_row = wm + (lsel & 1) * 8 + lrow;
    const int a_col = (lsel >> 1) * 4;            // u32 offset
    const int b_row = wn + (lsel >> 1) * 8 + lrow;
    const int b_col = (lsel & 1) * 4;

    const int m0 = blockIdx.y * BM;
    const int n0 = blockIdx.x * BN;
    const __half* AhB = Ah + (size_t)m0 * lda;
    const __half* AlB = Al + (size_t)m0 * lda;
    const __half* Bptr = Bw + (size_t)n0 * K;

    float acc[4][8][4];
#pragma unroll
    for (int mf = 0; mf < 4; mf++)
#pragma unroll
        for (int nf = 0; nf < 8; nf++)
#pragma unroll
            for (int r = 0; r < 4; r++) acc[mf][nf][r] = 0.f;

    const int NC = K / BK;

#pragma unroll
    for (int p = 0; p < 2; p++) {
        const uint32_t st = sb + p * STAGE_B;
        tile_async(AhB + p * BK, lda, st, tid);
        tile_async(AlB + p * BK, lda, st + TILE_B, tid);
        tile_async(Bptr + p * BK, K, st + 2 * TILE_B, tid);
        cp_commit();
    }

    for (int i = 0; i < NC; i++) {
        cp_wait1();
        __syncthreads();
        const int s = i & 1;
        const uint32_t stAh = sb + s * STAGE_B;
        const uint32_t stAl = stAh + TILE_B;
        const uint32_t stB  = stAh + 2 * TILE_B;
        const uint32_t aoff = (uint32_t)(a_row * TSTRIDE + a_col) * 4;
        const uint32_t boff = (uint32_t)(b_row * TSTRIDE + b_col) * 4;

#pragma unroll
        for (int ks = 0; ks < 2; ks++) {
            const uint32_t kb = (uint32_t)(ks * 8) * 4;   // byte offset in row
            uint32_t ah[4][4], al[4][4], b[8][2];
#pragma unroll
            for (int mf = 0; mf < 4; mf++) {
                const uint32_t ao = (uint32_t)(mf * 16 * TSTRIDE) * 4 + kb;
                ldsm_x4(ah[mf][0], ah[mf][1], ah[mf][2], ah[mf][3],
                        stAh + aoff + ao);
                ldsm_x4(al[mf][0], al[mf][1], al[mf][2], al[mf][3],
                        stAl + aoff + ao);
            }
#pragma unroll
            for (int p = 0; p < 4; p++) {                  // nf pairs
                const uint32_t bo = (uint32_t)(p * 16 * TSTRIDE) * 4 + kb;
                ldsm_x4(b[2*p][0], b[2*p][1], b[2*p+1][0], b[2*p+1][1],
                        stB + boff + bo);
            }
#pragma unroll
            for (int mf = 0; mf < 4; mf++)
#pragma unroll
                for (int nf = 0; nf < 8; nf++) {
                    mma_fp16(acc[mf][nf], ah[mf][0], ah[mf][1], ah[mf][2],
                             ah[mf][3], b[nf][0], b[nf][1]);
                    mma_fp16(acc[mf][nf], al[mf][0], al[mf][1], al[mf][2],
                             al[mf][3], b[nf][0], b[nf][1]);
                }
        }
        __syncthreads();
        if (i + 2 < NC) {
            const int k0 = (i + 2) * BK;
            const uint32_t st = sb + s * STAGE_B;
            tile_async(AhB + k0, lda, st, tid);
            tile_async(AlB + k0, lda, st + TILE_B, tid);
            tile_async(Bptr + k0, K, st + 2 * TILE_B, tid);
        }
        cp_commit();
    }

    // Epilogue
    const bool hilo = (Ch != nullptr);
#pragma unroll
    for (int mf = 0; mf < 4; mf++) {
        const int row0 = m0 + wm + mf * 16 + g;
#pragma unroll
        for (int nf = 0; nf < 8; nf++) {
            const int col = n0 + wn + nf * 8 + 2 * t;
            const float b0 = bias[col], b1 = bias[col + 1];
            float v00 = acc[mf][nf][0] + b0, v01 = acc[mf][nf][1] + b1;
            float v10 = acc[mf][nf][2] + b0, v11 = acc[mf][nf][3] + b1;
            *(float2*)(C + (size_t)row0 * N + col) = make_float2(v00, v01);
            *(float2*)(C + (size_t)(row0 + 8) * N + col) = make_float2(v10, v11);
            if (hilo) {
                size_t o0 = (size_t)row0 * N + col;
                size_t o1 = (size_t)(row0 + 8) * N + col;
                __half h;
                h = __float2half_rn(v00); Ch[o0] = h;
                Cl[o0] = __float2half_rn(v00 - __half2float(h));
                h = __float2half_rn(v01); Ch[o0 + 1] = h;
                Cl[o0 + 1] = __float2half_rn(v01 - __half2float(h));
                h = __float2half_rn(v10); Ch[o1] = h;
                Cl[o1] = __float2half_rn(v10 - __half2float(h));
                h = __float2half_rn(v11); Ch[o1 + 1] = h;
                Cl[o1 + 1] = __float2half_rn(v11 - __half2float(h));
            }
        }
    }
}

// ---------------------------------------------------------------------------
// Elementwise fp32 -> fp16 hi/lo split (for h_t)
// ---------------------------------------------------------------------------
__global__ void split_kernel(const float* __restrict__ src,
                             __half* __restrict__ hi,
                             __half* __restrict__ lo, int n)
{
    int i = (blockIdx.x * 256 + threadIdx.x) * 4;
    if (i >= n) return;
    float4 v = *(const float4*)(src + i);
    __half h0 = __float2half_rn(v.x);
    __half h1 = __float2half_rn(v.y);
    __half h2 = __float2half_rn(v.z);
    __half h3 = __float2half_rn(v.w);
    __half l0 = __float2half_rn(v.x - __half2float(h0));
    __half l1 = __float2half_rn(v.y - __half2float(h1));
    __half l2 = __float2half_rn(v.z - __half2float(h2));
    __half l3 = __float2half_rn(v.w - __half2float(h3));
    *(__half2*)(hi + i)     = __halves2half2(h0, h1);
    *(__half2*)(hi + i + 2) = __halves2half2(h2, h3);
    *(__half2*)(lo + i)     = __halves2half2(l0, l1);
    *(__half2*)(lo + i + 2) = __halves2half2(l2, l3);
}

// ---------------------------------------------------------------------------
// Transpose + fp16 round for weights: [rows,cols] fp32 -> [cols,rows] fp16
// ---------------------------------------------------------------------------
__global__ void transpose_half(const float* __restrict__ src,
                               __half* __restrict__ dst,
                               int rows, int cols)
{
    __shared__ float tile[32][33];
    const int c0 = blockIdx.x * 32, r0 = blockIdx.y * 32;
    for (int i = threadIdx.y; i < 32; i += 8)
        tile[i][threadIdx.x] = src[(size_t)(r0 + i) * cols + c0 + threadIdx.x];
    __syncthreads();
    for (int i = threadIdx.y; i < 32; i += 8)
        dst[(size_t)(c0 + i) * rows + r0 + threadIdx.x] =
            __float2half_rn(tile[threadIdx.x][i]);
}

__global__ void copyf(const float* __restrict__ s, float* __restrict__ d, int n)
{
    int i = blockIdx.x * 256 + threadIdx.x;
    if (i < n) d[i] = s[i];
}

// ---------------------------------------------------------------------------
// Per-token attention (rope fused). 256 threads / token. fp32 math.
// Emits hi/lo fp16 output for G4.
// ---------------------------------------------------------------------------
#define QK_STRIDE 193

__global__ void __launch_bounds__(256) attn_kernel(
    const float* __restrict__ s1, const float* __restrict__ s2,
    const float* __restrict__ s3,
    __half* __restrict__ obh, __half* __restrict__ obl)
{
    const float SCALER = 1.0f / sqrtf((float)(DH + DRH));
    const float LOG1E4 = 9.210340371976184f;

    int tk = blockIdx.x;
    int s = tk & (SS - 1);
    int tid = threadIdx.x;

    __shared__ float qf[HH][QK_STRIDE];
    __shared__ float kf[HH][QK_STRIDE];
    __shared__ float vv[HH][DH];
    __shared__ float sc[HH][HH];
    __shared__ float at[HH][HH];

    const float* qp  = s2 + (size_t)tk * 3072;
    const float* qrp = qp + 2048;
    const float* kp  = s3 + (size_t)tk * 4096;
    const float* vp  = kp + 2048;
    const float* krp = s1 + (size_t)tk * 2048 + 1024;

    for (int idx = tid; idx < HH * DH; idx += 256) {
        int h = idx >> 7, d = idx & 127;
        qf[h][d] = qp[idx];
        kf[h][d] = kp[idx];
        vv[h][d] = vp[idx];
    }
    for (int idx = tid; idx < HH * 32; idx += 256) {
        int h = idx >> 5, j = idx & 31;
        float invf = expf(-LOG1E4 * ((float)(2 * j) / 64.0f));
        float ang = (float)s * invf;
        float sj, cj;
        sincosf(ang, &sj, &cj);
        float x1q = qrp[h * DRH + j], x2q = qrp[h * DRH + j + 32];
        qf[h][DH + j]      = x1q * cj - x2q * sj;
        qf[h][DH + j + 32] = x2q * cj + x1q * sj;
        float x1k = krp[h * DRH + j], x2k = krp[h * DRH + j + 32];
        kf[h][DH + j]      = x1k * cj - x2k * sj;
        kf[h][DH + j + 32] = x2k * cj + x1k * sj;
    }
    __syncthreads();

    {
        int i = tid >> 4, j = tid & 15;
        float dsum = 0.f;
#pragma unroll 8
        for (int d = 0; d < DH + DRH; d++)
            dsum = fmaf(qf[i][d], kf[j][d], dsum);
        sc[i][j] = dsum * SCALER;
    }
    __syncthreads();

    if (tid < HH) {
        float mx = -1e30f;
#pragma unroll
        for (int j = 0; j < HH; j++) mx = fmaxf(mx, sc[tid][j]);
        float e[HH], sum = 0.f;
#pragma unroll
        for (int j = 0; j < HH; j++) { e[j] = expf(sc[tid][j] - mx); sum += e[j]; }
        float inv = 1.0f / sum;
#pragma unroll
        for (int j = 0; j < HH; j++) at[tid][j] = e[j] * inv;
    }
    __syncthreads();

    for (int idx = tid; idx < HH * DH; idx += 256) {
        int i = idx >> 7, d = idx & 127;
        float acc = 0.f;
#pragma unroll
        for (int j = 0; j < HH; j++)
            acc = fmaf(at[i][j], vv[j][d], acc);
        size_t o = (size_t)tk * DKQV + idx;
        __half h = __float2half_rn(acc);
        obh[o] = h;
        obl[o] = __float2half_rn(acc - __half2float(h));
    }
}

// ---------------------------------------------------------------------------
// Launch
// ---------------------------------------------------------------------------
static void launch_gemm(const __half* Ah, const __half* Al, int lda,
                        const __half* Bw, const float* bias, float* C,
                        __half* Ch, __half* Cl, int M, int N, int K)
{
    cudaFuncSetAttribute(gemm_fp16x2_kernel,
                         cudaFuncAttributeMaxDynamicSharedMemorySize, SMEM_BYTES);
    dim3 grid(N / BN, M / BM);
    gemm_fp16x2_kernel<<<grid, 128, SMEM_BYTES>>>(Ah, Al, lda, Bw, bias, C,
                                                  Ch, Cl, M, N, K);
}

static void launch_thalf(const float* src, __half* dst, int rows, int cols)
{
    dim3 grid(cols / 32, rows / 32), blk(32, 8);
    transpose_half<<<grid, blk>>>(src, dst, rows, cols);
}

static void launch_copy(const float* s, float* d, int n)
{
    copyf<<<(n + 255) / 256, 256>>>(s, d, n);
}

extern "C" void kernel_launch(void* const* d_in, const int* in_sizes, int n_in,
                              void* d_out, int out_size)
{
    const float* h_t  = (const float*)d_in[0];
    const float* Wc   = (const float*)d_in[1];
    const float* bc   = (const float*)d_in[2];
    const float* Wcq  = (const float*)d_in[3];
    const float* bcq  = (const float*)d_in[4];
    const float* Wqr  = (const float*)d_in[5];
    const float* bqr  = (const float*)d_in[6];
    const float* Wckv = (const float*)d_in[7];
    const float* bckv = (const float*)d_in[8];
    const float* Wck  = (const float*)d_in[9];
    const float* bck  = (const float*)d_in[10];
    const float* Wkr  = (const float*)d_in[11];
    const float* bkr  = (const float*)d_in[12];
    const float* Wv   = (const float*)d_in[13];
    const float* bv   = (const float*)d_in[14];
    const float* Wo   = (const float*)d_in[15];
    const float* bo   = (const float*)d_in[16];
    float* out = (float*)d_out;

    float *s1, *s2, *s3, *b1, *b2, *b3;
    __half *s1h, *s1l, *hth, *htl, *obh, *obl, *w1, *w2, *w3, *w4;
    cudaGetSymbolAddress((void**)&s1,  g_s1);
    cudaGetSymbolAddress((void**)&s1h, g_s1h);
    cudaGetSymbolAddress((void**)&s1l, g_s1l);
    cudaGetSymbolAddress((void**)&s2,  g_s2);
    cudaGetSymbolAddress((void**)&s3,  g_s3);
    cudaGetSymbolAddress((void**)&hth, g_hth);
    cudaGetSymbolAddress((void**)&htl, g_htl);
    cudaGetSymbolAddress((void**)&obh, g_obh);
    cudaGetSymbolAddress((void**)&obl, g_obl);
    cudaGetSymbolAddress((void**)&w1,  g_w1);
    cudaGetSymbolAddress((void**)&w2,  g_w2);
    cudaGetSymbolAddress((void**)&w3,  g_w3);
    cudaGetSymbolAddress((void**)&w4,  g_w4);
    cudaGetSymbolAddress((void**)&b1,  g_b1);
    cudaGetSymbolAddress((void**)&b2,  g_b2);
    cudaGetSymbolAddress((void**)&b3,  g_b3);

    // Pack: weights (transpose + fp16 round) and h_t (fp16 split)
    launch_thalf(Wc,   w1 + (size_t)0    * 2048, 2048, 512);
    launch_thalf(Wckv, w1 + (size_t)512  * 2048, 2048, 512);
    launch_thalf(Wkr,  w1 + (size_t)1024 * 2048, 2048, 1024);
    launch_thalf(Wcq,  w2 + (size_t)0    * 512,  512, 2048);
    launch_thalf(Wqr,  w2 + (size_t)2048 * 512,  512, 1024);
    launch_thalf(Wck,  w3 + (size_t)0    * 512,  512, 2048);
    launch_thalf(Wv,   w3 + (size_t)2048 * 512,  512, 2048);
    launch_thalf(Wo,   w4, 2048, 2048);
    launch_copy(bc,   b1,        512);
    launch_copy(bckv, b1 + 512,  512);
    launch_copy(bkr,  b1 + 1024, 1024);
    launch_copy(bcq,  b2,        2048);
    launch_copy(bqr,  b2 + 2048, 1024);
    launch_copy(bck,  b3,        2048);
    launch_copy(bv,   b3 + 2048, 2048);
    {
        int n = MTOK * 2048;
        split_kernel<<<(n / 4 + 255) / 256, 256>>>(h_t, hth, htl, n);
    }

    // G1: h_t -> (cq|ckv|kr), fp32 + hi/lo
    launch_gemm(hth, htl, 2048, w1, b1, s1, s1h, s1l, MTOK, 2048, 2048);
    // G2: cq -> (q|qr)
    launch_gemm(s1h, s1l, 2048, w2, b2, s2, nullptr, nullptr, MTOK, 3072, 512);
    // G3: ckv -> (k|v)
    launch_gemm(s1h + 512, s1l + 512, 2048, w3, b3, s3, nullptr, nullptr,
                MTOK, 4096, 512);
    // attention -> hi/lo fp16
    attn_kernel<<<MTOK, 256>>>(s1, s2, s3, obh, obl);
    // G4: o -> out
    launch_gemm(obh, obl, 2048, w4, bo, out, nullptr, nullptr, MTOK, 2048, 2048);
}

// round 15
// speedup vs baseline: 2.4434x; 1.6384x over previous
#include <cuda_runtime.h>
#include <cuda_fp16.h>
#include <math.h>
#include <stdint.h>

// ---------------------------------------------------------------------------
// Problem constants
// ---------------------------------------------------------------------------
#define BB 2
#define SS 4096
#define HH 16
#define DKQV 2048
#define DH 128
#define DRH 64
#define MTOK (BB*SS)            // 8192 tokens

// ---------------------------------------------------------------------------
// Device scratch
// ---------------------------------------------------------------------------
__device__ float g_s1 [MTOK * 2048];                       // cq | ckv | kr (fp32)
__device__ __half g_s1h[MTOK * 2048];                      // fp16 copy
__device__ float g_s2 [MTOK * 3072];                       // q | qr
__device__ float g_s3 [MTOK * 4096];                       // k | v
__device__ __half g_hth[MTOK * 2048];                      // h_t fp16
__device__ __half g_obh[MTOK * 2048];                      // attn out fp16
__device__ __half g_w1[2048 * 2048];                       // (Wc|Wckv|Wkr)^T fp16
__device__ __half g_w2[3072 * 512];                        // (Wcq|Wqr)^T
__device__ __half g_w3[4096 * 512];                        // (Wck|Wv)^T
__device__ __half g_w4[2048 * 2048];                       // Wo^T
__device__ float g_b1 [2048];
__device__ float g_b2 [3072];
__device__ float g_b3 [4096];

// ---------------------------------------------------------------------------
// GEMM config: CTA 128x128, BK=32, 128 threads (4 warps of 64x64), 2 stages
// fp16 tiles [128 rows][32 k] in smem, row stride 20 u32 (16 data + 4 pad).
// stride 20: (r*20 mod 32)/4 permutes the eight 4-bank groups -> every
// ldmatrix 8-row phase is conflict-free.
// ---------------------------------------------------------------------------
#define BM 128
#define BN 128
#define BK 32
#define TSTRIDE 20
#define TILE_B (128 * TSTRIDE * 4)      // 10240 bytes
#define STAGE_B (2 * TILE_B)            // A, B = 20480
#define SMEM_BYTES (2 * STAGE_B)        // 40960 -> 2 CTAs/SM

__device__ __forceinline__ uint32_t smem_u32(const void* p) {
    uint32_t a;
    asm("{ .reg .u64 t; cvta.to.shared.u64 t, %1; cvt.u32.u64 %0, t; }"
        : "=r"(a) : "l"(p));
    return a;
}
__device__ __forceinline__ void cp_async16(uint32_t dst, const void* src) {
    asm volatile("cp.async.cg.shared.global [%0], [%1], 16;"
                 :: "r"(dst), "l"(src) : "memory");
}
__device__ __forceinline__ void cp_commit() {
    asm volatile("cp.async.commit_group;" ::: "memory");
}
__device__ __forceinline__ void cp_wait1() {
    asm volatile("cp.async.wait_group 1;" ::: "memory");
}

__device__ __forceinline__ void mma_fp16(float c[4], uint32_t a0, uint32_t a1,
                                         uint32_t a2, uint32_t a3,
                                         uint32_t b0, uint32_t b1) {
    asm volatile(
        "mma.sync.aligned.m16n8k16.row.col.f32.f16.f16.f32 "
        "{%0,%1,%2,%3}, {%4,%5,%6,%7}, {%8,%9}, {%0,%1,%2,%3};"
        : "+f"(c[0]), "+f"(c[1]), "+f"(c[2]), "+f"(c[3])
        : "r"(a0), "r"(a1), "r"(a2), "r"(a3), "r"(b0), "r"(b1));
}

__device__ __forceinline__ void ldsm_x4(uint32_t& r0, uint32_t& r1,
                                        uint32_t& r2, uint32_t& r3,
                                        uint32_t addr) {
    asm volatile("ldmatrix.sync.aligned.m8n8.x4.shared.b16 {%0,%1,%2,%3}, [%4];"
                 : "=r"(r0), "=r"(r1), "=r"(r2), "=r"(r3) : "r"(addr));
}

// fp16 [row,K] tile (128 rows x 32 cols = 64B/row) -> smem [128][20 u32]
__device__ __forceinline__ void tile_async(const __half* __restrict__ g,
                                           int ld, uint32_t sbase, int tid) {
#pragma unroll
    for (int j = 0; j < 4; j++) {
        int idx = tid + j * 128;       // 0..511
        int r = idx >> 2, c = idx & 3; // 4 x 16B chunks per row
        cp_async16(sbase + (uint32_t)(r * TSTRIDE + c * 4) * 4,
                   g + (size_t)r * ld + c * 8);
    }
}

// ---------------------------------------------------------------------------
// fp16 GEMM: C = A[M,K] @ B[N,K]^T + bias, fp32 accumulate.
// Optionally also emits an fp16 copy of C. grid(N/128, M/128), 128 thr.
// ---------------------------------------------------------------------------
__global__ void __launch_bounds__(128, 2) gemm_fp16_kernel(
    const __half* __restrict__ A, int lda,
    const __half* __restrict__ Bw,
    const float* __restrict__ bias,
    float* __restrict__ C,
    __half* __restrict__ Ch,       // may be null
    int M, int N, int K)
{
    extern __shared__ float smem[];
    const uint32_t sb = smem_u32(smem);
    const int tid = threadIdx.x;
    const int wid = tid >> 5;
    const int lane = tid & 31;
    const int g = lane >> 2;
    const int t = lane & 3;
    const int wm = (wid & 1) * 64;
    const int wn = (wid >> 1) * 64;

    // ldmatrix per-lane address components
    const int lrow = lane & 7;
    const int lsel = lane >> 3;
    const int a_row = wm + (lsel & 1) * 8 + lrow;
    const int a_col = (lsel >> 1) * 4;            // u32 offset
    const int b_row = wn + (lsel >> 1) * 8 + lrow;
    const int b_col = (lsel & 1) * 4;

    const int m0 = blockIdx.y * BM;
    const int n0 = blockIdx.x * BN;
    const __half* Aptr = A + (size_t)m0 * lda;
    const __half* Bptr = Bw + (size_t)n0 * K;

    float acc[4][8][4];
#pragma unroll
    for (int mf = 0; mf < 4; mf++)
#pragma unroll
        for (int nf = 0; nf < 8; nf++)
#pragma unroll
            for (int r = 0; r < 4; r++) acc[mf][nf][r] = 0.f;

    const int NC = K / BK;

#pragma unroll
    for (int p = 0; p < 2; p++) {
        const uint32_t st = sb + p * STAGE_B;
        tile_async(Aptr + p * BK, lda, st, tid);
        tile_async(Bptr + p * BK, K, st + TILE_B, tid);
        cp_commit();
    }

    for (int i = 0; i < NC; i++) {
        cp_wait1();
        __syncthreads();
        const int s = i & 1;
        const uint32_t stA = sb + s * STAGE_B;
        const uint32_t stB = stA + TILE_B;
        const uint32_t aoff = (uint32_t)(a_row * TSTRIDE + a_col) * 4;
        const uint32_t boff = (uint32_t)(b_row * TSTRIDE + b_col) * 4;

#pragma unroll
        for (int ks = 0; ks < 2; ks++) {
            const uint32_t kb = (uint32_t)(ks * 8) * 4;
            uint32_t a[4][4], b[8][2];
#pragma unroll
            for (int mf = 0; mf < 4; mf++) {
                const uint32_t ao = (uint32_t)(mf * 16 * TSTRIDE) * 4 + kb;
                ldsm_x4(a[mf][0], a[mf][1], a[mf][2], a[mf][3],
                        stA + aoff + ao);
            }
#pragma unroll
            for (int p = 0; p < 4; p++) {
                const uint32_t bo = (uint32_t)(p * 16 * TSTRIDE) * 4 + kb;
                ldsm_x4(b[2*p][0], b[2*p][1], b[2*p+1][0], b[2*p+1][1],
                        stB + boff + bo);
            }
#pragma unroll
            for (int mf = 0; mf < 4; mf++)
#pragma unroll
                for (int nf = 0; nf < 8; nf++)
                    mma_fp16(acc[mf][nf], a[mf][0], a[mf][1], a[mf][2],
                             a[mf][3], b[nf][0], b[nf][1]);
        }
        __syncthreads();
        if (i + 2 < NC) {
            const int k0 = (i + 2) * BK;
            const uint32_t st = sb + s * STAGE_B;
            tile_async(Aptr + k0, lda, st, tid);
            tile_async(Bptr + k0, K, st + TILE_B, tid);
        }
        cp_commit();
    }

    // Epilogue
    const bool emith = (Ch != nullptr);
#pragma unroll
    for (int mf = 0; mf < 4; mf++) {
        const int row0 = m0 + wm + mf * 16 + g;
#pragma unroll
        for (int nf = 0; nf < 8; nf++) {
            const int col = n0 + wn + nf * 8 + 2 * t;
            const float b0 = bias[col], b1 = bias[col + 1];
            float v00 = acc[mf][nf][0] + b0, v01 = acc[mf][nf][1] + b1;
            float v10 = acc[mf][nf][2] + b0, v11 = acc[mf][nf][3] + b1;
            *(float2*)(C + (size_t)row0 * N + col) = make_float2(v00, v01);
            *(float2*)(C + (size_t)(row0 + 8) * N + col) = make_float2(v10, v11);
            if (emith) {
                *(__half2*)(Ch + (size_t)row0 * N + col) =
                    __halves2half2(__float2half_rn(v00), __float2half_rn(v01));
                *(__half2*)(Ch + (size_t)(row0 + 8) * N + col) =
                    __halves2half2(__float2half_rn(v10), __float2half_rn(v11));
            }
        }
    }
}

// ---------------------------------------------------------------------------
// Elementwise fp32 -> fp16 convert (for h_t)
// ---------------------------------------------------------------------------
__global__ void convert_kernel(const float* __restrict__ src,
                               __half* __restrict__ dst, int n)
{
    int i = (blockIdx.x * 256 + threadIdx.x) * 4;
    if (i >= n) return;
    float4 v = *(const float4*)(src + i);
    *(__half2*)(dst + i)     = __halves2half2(__float2half_rn(v.x),
                                              __float2half_rn(v.y));
    *(__half2*)(dst + i + 2) = __halves2half2(__float2half_rn(v.z),
                                              __float2half_rn(v.w));
}

// ---------------------------------------------------------------------------
// Transpose + fp16 round for weights: [rows,cols] fp32 -> [cols,rows] fp16
// ---------------------------------------------------------------------------
__global__ void transpose_half(const float* __restrict__ src,
                               __half* __restrict__ dst,
                               int rows, int cols)
{
    __shared__ float tile[32][33];
    const int c0 = blockIdx.x * 32, r0 = blockIdx.y * 32;
    for (int i = threadIdx.y; i < 32; i += 8)
        tile[i][threadIdx.x] = src[(size_t)(r0 + i) * cols + c0 + threadIdx.x];
    __syncthreads();
    for (int i = threadIdx.y; i < 32; i += 8)
        dst[(size_t)(c0 + i) * rows + r0 + threadIdx.x] =
            __float2half_rn(tile[threadIdx.x][i]);
}

__global__ void copyf(const float* __restrict__ s, float* __restrict__ d, int n)
{
    int i = blockIdx.x * 256 + threadIdx.x;
    if (i < n) d[i] = s[i];
}

// ---------------------------------------------------------------------------
// Per-token attention (rope fused). 256 threads / token. fp32 math.
// Emits fp16 output for G4.
// ---------------------------------------------------------------------------
#define QK_STRIDE 193

__global__ void __launch_bounds__(256) attn_kernel(
    const float* __restrict__ s1, const float* __restrict__ s2,
    const float* __restrict__ s3,
    __half* __restrict__ obh)
{
    const float SCALER = 1.0f / sqrtf((float)(DH + DRH));
    const float LOG1E4 = 9.210340371976184f;

    int tk = blockIdx.x;
    int s = tk & (SS - 1);
    int tid = threadIdx.x;

    __shared__ float qf[HH][QK_STRIDE];
    __shared__ float kf[HH][QK_STRIDE];
    __shared__ float vv[HH][DH];
    __shared__ float sc[HH][HH];
    __shared__ float at[HH][HH];

    const float* qp  = s2 + (size_t)tk * 3072;
    const float* qrp = qp + 2048;
    const float* kp  = s3 + (size_t)tk * 4096;
    const float* vp  = kp + 2048;
    const float* krp = s1 + (size_t)tk * 2048 + 1024;

    for (int idx = tid; idx < HH * DH; idx += 256) {
        int h = idx >> 7, d = idx & 127;
        qf[h][d] = qp[idx];
        kf[h][d] = kp[idx];
        vv[h][d] = vp[idx];
    }
    for (int idx = tid; idx < HH * 32; idx += 256) {
        int h = idx >> 5, j = idx & 31;
        float invf = expf(-LOG1E4 * ((float)(2 * j) / 64.0f));
        float ang = (float)s * invf;
        float sj, cj;
        sincosf(ang, &sj, &cj);
        float x1q = qrp[h * DRH + j], x2q = qrp[h * DRH + j + 32];
        qf[h][DH + j]      = x1q * cj - x2q * sj;
        qf[h][DH + j + 32] = x2q * cj + x1q * sj;
        float x1k = krp[h * DRH + j], x2k = krp[h * DRH + j + 32];
        kf[h][DH + j]      = x1k * cj - x2k * sj;
        kf[h][DH + j + 32] = x2k * cj + x1k * sj;
    }
    __syncthreads();

    {
        int i = tid >> 4, j = tid & 15;
        float dsum = 0.f;
#pragma unroll 8
        for (int d = 0; d < DH + DRH; d++)
            dsum = fmaf(qf[i][d], kf[j][d], dsum);
        sc[i][j] = dsum * SCALER;
    }
    __syncthreads();

    if (tid < HH) {
        float mx = -1e30f;
#pragma unroll
        for (int j = 0; j < HH; j++) mx = fmaxf(mx, sc[tid][j]);
        float e[HH], sum = 0.f;
#pragma unroll
        for (int j = 0; j < HH; j++) { e[j] = expf(sc[tid][j] - mx); sum += e[j]; }
        float inv = 1.0f / sum;
#pragma unroll
        for (int j = 0; j < HH; j++) at[tid][j] = e[j] * inv;
    }
    __syncthreads();

    for (int idx = tid; idx < HH * DH; idx += 256) {
        int i = idx >> 7, d = idx & 127;
        float acc = 0.f;
#pragma unroll
        for (int j = 0; j < HH; j++)
            acc = fmaf(at[i][j], vv[j][d], acc);
        obh[(size_t)tk * DKQV + idx] = __float2half_rn(acc);
    }
}

// ---------------------------------------------------------------------------
// Launch
// ---------------------------------------------------------------------------
static void launch_gemm(const __half* A, int lda, const __half* Bw,
                        const float* bias, float* C, __half* Ch,
                        int M, int N, int K)
{
    cudaFuncSetAttribute(gemm_fp16_kernel,
                         cudaFuncAttributeMaxDynamicSharedMemorySize, SMEM_BYTES);
    dim3 grid(N / BN, M / BM);
    gemm_fp16_kernel<<<grid, 128, SMEM_BYTES>>>(A, lda, Bw, bias, C, Ch, M, N, K);
}

static void launch_thalf(const float* src, __half* dst, int rows, int cols)
{
    dim3 grid(cols / 32, rows / 32), blk(32, 8);
    transpose_half<<<grid, blk>>>(src, dst, rows, cols);
}

static void launch_copy(const float* s, float* d, int n)
{
    copyf<<<(n + 255) / 256, 256>>>(s, d, n);
}

extern "C" void kernel_launch(void* const* d_in, const int* in_sizes, int n_in,
                              void* d_out, int out_size)
{
    const float* h_t  = (const float*)d_in[0];
    const float* Wc   = (const float*)d_in[1];
    const float* bc   = (const float*)d_in[2];
    const float* Wcq  = (const float*)d_in[3];
    const float* bcq  = (const float*)d_in[4];
    const float* Wqr  = (const float*)d_in[5];
    const float* bqr  = (const float*)d_in[6];
    const float* Wckv = (const float*)d_in[7];
    const float* bckv = (const float*)d_in[8];
    const float* Wck  = (const float*)d_in[9];
    const float* bck  = (const float*)d_in[10];
    const float* Wkr  = (const float*)d_in[11];
    const float* bkr  = (const float*)d_in[12];
    const float* Wv   = (const float*)d_in[13];
    const float* bv   = (const float*)d_in[14];
    const float* Wo   = (const float*)d_in[15];
    const float* bo   = (const float*)d_in[16];
    float* out = (float*)d_out;

    float *s1, *s2, *s3, *b1, *b2, *b3;
    __half *s1h, *hth, *obh, *w1, *w2, *w3, *w4;
    cudaGetSymbolAddress((void**)&s1,  g_s1);
    cudaGetSymbolAddress((void**)&s1h, g_s1h);
    cudaGetSymbolAddress((void**)&s2,  g_s2);
    cudaGetSymbolAddress((void**)&s3,  g_s3);
    cudaGetSymbolAddress((void**)&hth, g_hth);
    cudaGetSymbolAddress((void**)&obh, g_obh);
    cudaGetSymbolAddress((void**)&w1,  g_w1);
    cudaGetSymbolAddress((void**)&w2,  g_w2);
    cudaGetSymbolAddress((void**)&w3,  g_w3);
    cudaGetSymbolAddress((void**)&w4,  g_w4);
    cudaGetSymbolAddress((void**)&b1,  g_b1);
    cudaGetSymbolAddress((void**)&b2,  g_b2);
    cudaGetSymbolAddress((void**)&b3,  g_b3);

    // Pack: weights (transpose + fp16 round) and h_t (fp16 convert)
    launch_thalf(Wc,   w1 + (size_t)0    * 2048, 2048, 512);
    launch_thalf(Wckv, w1 + (size_t)512  * 2048, 2048, 512);
    launch_thalf(Wkr,  w1 + (size_t)1024 * 2048, 2048, 1024);
    launch_thalf(Wcq,  w2 + (size_t)0    * 512,  512, 2048);
    launch_thalf(Wqr,  w2 + (size_t)2048 * 512,  512, 1024);
    launch_thalf(Wck,  w3 + (size_t)0    * 512,  512, 2048);
    launch_thalf(Wv,   w3 + (size_t)2048 * 512,  512, 2048);
    launch_thalf(Wo,   w4, 2048, 2048);
    launch_copy(bc,   b1,        512);
    launch_copy(bckv, b1 + 512,  512);
    launch_copy(bkr,  b1 + 1024, 1024);
    launch_copy(bcq,  b2,        2048);
    launch_copy(bqr,  b2 + 2048, 1024);
    launch_copy(bck,  b3,        2048);
    launch_copy(bv,   b3 + 2048, 2048);
    {
        int n = MTOK * 2048;
        convert_kernel<<<(n / 4 + 255) / 256, 256>>>(h_t, hth, n);
    }

    // G1: h_t -> (cq|ckv|kr), fp32 + fp16 copy
    launch_gemm(hth, 2048, w1, b1, s1, s1h, MTOK, 2048, 2048);
    // G2: cq -> (q|qr)
    launch_gemm(s1h, 2048, w2, b2, s2, nullptr, MTOK, 3072, 512);
    // G3: ckv -> (k|v)
    launch_gemm(s1h + 512, 2048, w3, b3, s3, nullptr, MTOK, 4096, 512);
    // attention -> fp16
    attn_kernel<<<MTOK, 256>>>(s1, s2, s3, obh);
    // G4: o -> out
    launch_gemm(obh, 2048, w4, bo, out, nullptr, MTOK, 2048, 2048);
}

// round 16
// speedup vs baseline: 2.5288x; 1.0350x over previous
#include <cuda_runtime.h>
#include <cuda_fp16.h>
#include <math.h>
#include <stdint.h>

// ---------------------------------------------------------------------------
// Problem constants
// ---------------------------------------------------------------------------
#define BB 2
#define SS 4096
#define HH 16
#define DKQV 2048
#define DH 128
#define DRH 64
#define MTOK (BB*SS)            // 8192 tokens

// ---------------------------------------------------------------------------
// Device scratch (fp16 everywhere except final output)
// ---------------------------------------------------------------------------
__device__ __half g_s1h[MTOK * 2048];                      // cq | ckv | kr
__device__ __half g_s2h[MTOK * 3072];                      // q | qr
__device__ __half g_s3h[MTOK * 4096];                      // k | v
__device__ __half g_hth[MTOK * 2048];                      // h_t fp16
__device__ __half g_obh[MTOK * 2048];                      // attn out fp16
__device__ __half g_w1[2048 * 2048];                       // (Wc|Wckv|Wkr)^T fp16
__device__ __half g_w2[3072 * 512];                        // (Wcq|Wqr)^T
__device__ __half g_w3[4096 * 512];                        // (Wck|Wv)^T
__device__ __half g_w4[2048 * 2048];                       // Wo^T
__device__ float g_b1 [2048];
__device__ float g_b2 [3072];
__device__ float g_b3 [4096];

// ---------------------------------------------------------------------------
// GEMM config: CTA 128x128, BK=32, 128 threads (4 warps of 64x64), 2 stages
// fp16 tiles [128 rows][32 k] in smem, row stride 20 u32 (16 data + 4 pad).
// ---------------------------------------------------------------------------
#define BM 128
#define BN 128
#define BK 32
#define TSTRIDE 20
#define TILE_B (128 * TSTRIDE * 4)      // 10240 bytes
#define STAGE_B (2 * TILE_B)            // A, B = 20480
#define SMEM_BYTES (2 * STAGE_B)        // 40960 -> 2 CTAs/SM

__device__ __forceinline__ uint32_t smem_u32(const void* p) {
    uint32_t a;
    asm("{ .reg .u64 t; cvta.to.shared.u64 t, %1; cvt.u32.u64 %0, t; }"
        : "=r"(a) : "l"(p));
    return a;
}
__device__ __forceinline__ void cp_async16(uint32_t dst, const void* src) {
    asm volatile("cp.async.cg.shared.global [%0], [%1], 16;"
                 :: "r"(dst), "l"(src) : "memory");
}
__device__ __forceinline__ void cp_commit() {
    asm volatile("cp.async.commit_group;" ::: "memory");
}
__device__ __forceinline__ void cp_wait1() {
    asm volatile("cp.async.wait_group 1;" ::: "memory");
}

__device__ __forceinline__ void mma_fp16(float c[4], uint32_t a0, uint32_t a1,
                                         uint32_t a2, uint32_t a3,
                                         uint32_t b0, uint32_t b1) {
    asm volatile(
        "mma.sync.aligned.m16n8k16.row.col.f32.f16.f16.f32 "
        "{%0,%1,%2,%3}, {%4,%5,%6,%7}, {%8,%9}, {%0,%1,%2,%3};"
        : "+f"(c[0]), "+f"(c[1]), "+f"(c[2]), "+f"(c[3])
        : "r"(a0), "r"(a1), "r"(a2), "r"(a3), "r"(b0), "r"(b1));
}

__device__ __forceinline__ void ldsm_x4(uint32_t& r0, uint32_t& r1,
                                        uint32_t& r2, uint32_t& r3,
                                        uint32_t addr) {
    asm volatile("ldmatrix.sync.aligned.m8n8.x4.shared.b16 {%0,%1,%2,%3}, [%4];"
                 : "=r"(r0), "=r"(r1), "=r"(r2), "=r"(r3) : "r"(addr));
}

// fp16 [row,K] tile (128 rows x 32 cols = 64B/row) -> smem [128][20 u32]
__device__ __forceinline__ void tile_async(const __half* __restrict__ g,
                                           int ld, uint32_t sbase, int tid) {
#pragma unroll
    for (int j = 0; j < 4; j++) {
        int idx = tid + j * 128;       // 0..511
        int r = idx >> 2, c = idx & 3; // 4 x 16B chunks per row
        cp_async16(sbase + (uint32_t)(r * TSTRIDE + c * 4) * 4,
                   g + (size_t)r * ld + c * 8);
    }
}

// ---------------------------------------------------------------------------
// fp16 GEMM: C = A[M,K] @ B[N,K]^T + bias, fp32 accumulate.
// Emits fp32 C (if non-null) and/or fp16 Ch (if non-null).
// grid(N/128, M/128), 128 thr.
// ---------------------------------------------------------------------------
__global__ void __launch_bounds__(128, 2) gemm_fp16_kernel(
    const __half* __restrict__ A, int lda,
    const __half* __restrict__ Bw,
    const float* __restrict__ bias,
    float* __restrict__ C,         // may be null
    __half* __restrict__ Ch,       // may be null
    int M, int N, int K)
{
    extern __shared__ float smem[];
    const uint32_t sb = smem_u32(smem);
    const int tid = threadIdx.x;
    const int lane = tid & 31;
    const int wid = tid >> 5;
    const int g = lane >> 2;
    const int t = lane & 3;
    const int wm = (wid & 1) * 64;
    const int wn = (wid >> 1) * 64;

    const int lrow = lane & 7;
    const int lsel = lane >> 3;
    const int a_row = wm + (lsel & 1) * 8 + lrow;
    const int a_col = (lsel >> 1) * 4;
    const int b_row = wn + (lsel >> 1) * 8 + lrow;
    const int b_col = (lsel & 1) * 4;

    const int m0 = blockIdx.y * BM;
    const int n0 = blockIdx.x * BN;
    const __half* Aptr = A + (size_t)m0 * lda;
    const __half* Bptr = Bw + (size_t)n0 * K;

    float acc[4][8][4];
#pragma unroll
    for (int mf = 0; mf < 4; mf++)
#pragma unroll
        for (int nf = 0; nf < 8; nf++)
#pragma unroll
            for (int r = 0; r < 4; r++) acc[mf][nf][r] = 0.f;

    const int NC = K / BK;

#pragma unroll
    for (int p = 0; p < 2; p++) {
        const uint32_t st = sb + p * STAGE_B;
        tile_async(Aptr + p * BK, lda, st, tid);
        tile_async(Bptr + p * BK, K, st + TILE_B, tid);
        cp_commit();
    }

    for (int i = 0; i < NC; i++) {
        cp_wait1();
        __syncthreads();
        const int s = i & 1;
        const uint32_t stA = sb + s * STAGE_B;
        const uint32_t stB = stA + TILE_B;
        const uint32_t aoff = (uint32_t)(a_row * TSTRIDE + a_col) * 4;
        const uint32_t boff = (uint32_t)(b_row * TSTRIDE + b_col) * 4;

#pragma unroll
        for (int ks = 0; ks < 2; ks++) {
            const uint32_t kb = (uint32_t)(ks * 8) * 4;
            uint32_t a[4][4], b[8][2];
#pragma unroll
            for (int mf = 0; mf < 4; mf++) {
                const uint32_t ao = (uint32_t)(mf * 16 * TSTRIDE) * 4 + kb;
                ldsm_x4(a[mf][0], a[mf][1], a[mf][2], a[mf][3],
                        stA + aoff + ao);
            }
#pragma unroll
            for (int p = 0; p < 4; p++) {
                const uint32_t bo = (uint32_t)(p * 16 * TSTRIDE) * 4 + kb;
                ldsm_x4(b[2*p][0], b[2*p][1], b[2*p+1][0], b[2*p+1][1],
                        stB + boff + bo);
            }
#pragma unroll
            for (int mf = 0; mf < 4; mf++)
#pragma unroll
                for (int nf = 0; nf < 8; nf++)
                    mma_fp16(acc[mf][nf], a[mf][0], a[mf][1], a[mf][2],
                             a[mf][3], b[nf][0], b[nf][1]);
        }
        __syncthreads();
        if (i + 2 < NC) {
            const int k0 = (i + 2) * BK;
            const uint32_t st = sb + s * STAGE_B;
            tile_async(Aptr + k0, lda, st, tid);
            tile_async(Bptr + k0, K, st + TILE_B, tid);
        }
        cp_commit();
    }

    // Epilogue
    const bool emitf = (C != nullptr);
    const bool emith = (Ch != nullptr);
#pragma unroll
    for (int mf = 0; mf < 4; mf++) {
        const int row0 = m0 + wm + mf * 16 + g;
#pragma unroll
        for (int nf = 0; nf < 8; nf++) {
            const int col = n0 + wn + nf * 8 + 2 * t;
            const float b0 = bias[col], b1 = bias[col + 1];
            float v00 = acc[mf][nf][0] + b0, v01 = acc[mf][nf][1] + b1;
            float v10 = acc[mf][nf][2] + b0, v11 = acc[mf][nf][3] + b1;
            if (emitf) {
                *(float2*)(C + (size_t)row0 * N + col) = make_float2(v00, v01);
                *(float2*)(C + (size_t)(row0 + 8) * N + col) = make_float2(v10, v11);
            }
            if (emith) {
                *(__half2*)(Ch + (size_t)row0 * N + col) =
                    __halves2half2(__float2half_rn(v00), __float2half_rn(v01));
                *(__half2*)(Ch + (size_t)(row0 + 8) * N + col) =
                    __halves2half2(__float2half_rn(v10), __float2half_rn(v11));
            }
        }
    }
}

// ---------------------------------------------------------------------------
// Elementwise fp32 -> fp16 convert (for h_t)
// ---------------------------------------------------------------------------
__global__ void convert_kernel(const float* __restrict__ src,
                               __half* __restrict__ dst, int n)
{
    int i = (blockIdx.x * 256 + threadIdx.x) * 4;
    if (i >= n) return;
    float4 v = *(const float4*)(src + i);
    *(__half2*)(dst + i)     = __halves2half2(__float2half_rn(v.x),
                                              __float2half_rn(v.y));
    *(__half2*)(dst + i + 2) = __halves2half2(__float2half_rn(v.z),
                                              __float2half_rn(v.w));
}

// ---------------------------------------------------------------------------
// Transpose + fp16 round for weights: [rows,cols] fp32 -> [cols,rows] fp16
// ---------------------------------------------------------------------------
__global__ void transpose_half(const float* __restrict__ src,
                               __half* __restrict__ dst,
                               int rows, int cols)
{
    __shared__ float tile[32][33];
    const int c0 = blockIdx.x * 32, r0 = blockIdx.y * 32;
    for (int i = threadIdx.y; i < 32; i += 8)
        tile[i][threadIdx.x] = src[(size_t)(r0 + i) * cols + c0 + threadIdx.x];
    __syncthreads();
    for (int i = threadIdx.y; i < 32; i += 8)
        dst[(size_t)(c0 + i) * rows + r0 + threadIdx.x] =
            __float2half_rn(tile[threadIdx.x][i]);
}

__global__ void copyf(const float* __restrict__ s, float* __restrict__ d, int n)
{
    int i = blockIdx.x * 256 + threadIdx.x;
    if (i < n) d[i] = s[i];
}

// ---------------------------------------------------------------------------
// Per-token attention (rope fused). 256 threads / token.
// fp16 inputs (q|qr from s2h, k|v from s3h, kr from s1h), fp32 math,
// fp16 output for G4.
// ---------------------------------------------------------------------------
#define QK_STRIDE 193

__global__ void __launch_bounds__(256) attn_kernel(
    const __half* __restrict__ s1h, const __half* __restrict__ s2h,
    const __half* __restrict__ s3h,
    __half* __restrict__ obh)
{
    const float SCALER = 1.0f / sqrtf((float)(DH + DRH));
    const float LOG1E4 = 9.210340371976184f;

    int tk = blockIdx.x;
    int s = tk & (SS - 1);
    int tid = threadIdx.x;

    __shared__ float qf[HH][QK_STRIDE];
    __shared__ float kf[HH][QK_STRIDE];
    __shared__ float vv[HH][DH];
    __shared__ float sc[HH][HH];
    __shared__ float at[HH][HH];

    const __half* qp  = s2h + (size_t)tk * 3072;
    const __half* qrp = qp + 2048;
    const __half* kp  = s3h + (size_t)tk * 4096;
    const __half* vp  = kp + 2048;
    const __half* krp = s1h + (size_t)tk * 2048 + 1024;

    // base parts: 2048 halves each, half2 vectorized (1024 pairs)
    for (int p = tid; p < HH * DH / 2; p += 256) {
        int idx = p * 2;
        int h = idx >> 7, d = idx & 127;
        float2 q2 = __half22float2(*(const __half2*)(qp + idx));
        float2 k2 = __half22float2(*(const __half2*)(kp + idx));
        float2 v2 = __half22float2(*(const __half2*)(vp + idx));
        qf[h][d] = q2.x; qf[h][d + 1] = q2.y;
        kf[h][d] = k2.x; kf[h][d + 1] = k2.y;
        vv[h][d] = v2.x; vv[h][d + 1] = v2.y;
    }
    // rope parts: 16 heads x 32 rotation pairs
    for (int idx = tid; idx < HH * 32; idx += 256) {
        int h = idx >> 5, j = idx & 31;
        float invf = expf(-LOG1E4 * ((float)(2 * j) / 64.0f));
        float ang = (float)s * invf;
        float sj, cj;
        sincosf(ang, &sj, &cj);
        float x1q = __half2float(qrp[h * DRH + j]);
        float x2q = __half2float(qrp[h * DRH + j + 32]);
        qf[h][DH + j]      = x1q * cj - x2q * sj;
        qf[h][DH + j + 32] = x2q * cj + x1q * sj;
        float x1k = __half2float(krp[h * DRH + j]);
        float x2k = __half2float(krp[h * DRH + j + 32]);
        kf[h][DH + j]      = x1k * cj - x2k * sj;
        kf[h][DH + j + 32] = x2k * cj + x1k * sj;
    }
    __syncthreads();

    {
        int i = tid >> 4, j = tid & 15;
        float dsum = 0.f;
#pragma unroll 8
        for (int d = 0; d < DH + DRH; d++)
            dsum = fmaf(qf[i][d], kf[j][d], dsum);
        sc[i][j] = dsum * SCALER;
    }
    __syncthreads();

    if (tid < HH) {
        float mx = -1e30f;
#pragma unroll
        for (int j = 0; j < HH; j++) mx = fmaxf(mx, sc[tid][j]);
        float e[HH], sum = 0.f;
#pragma unroll
        for (int j = 0; j < HH; j++) { e[j] = expf(sc[tid][j] - mx); sum += e[j]; }
        float inv = 1.0f / sum;
#pragma unroll
        for (int j = 0; j < HH; j++) at[tid][j] = e[j] * inv;
    }
    __syncthreads();

    for (int p = tid; p < HH * DH / 2; p += 256) {
        int idx = p * 2;
        int i = idx >> 7, d = idx & 127;
        float a0 = 0.f, a1 = 0.f;
#pragma unroll
        for (int j = 0; j < HH; j++) {
            float w = at[i][j];
            a0 = fmaf(w, vv[j][d], a0);
            a1 = fmaf(w, vv[j][d + 1], a1);
        }
        *(__half2*)(obh + (size_t)tk * DKQV + idx) =
            __halves2half2(__float2half_rn(a0), __float2half_rn(a1));
    }
}

// ---------------------------------------------------------------------------
// Launch
// ---------------------------------------------------------------------------
static void launch_gemm(const __half* A, int lda, const __half* Bw,
                        const float* bias, float* C, __half* Ch,
                        int M, int N, int K)
{
    cudaFuncSetAttribute(gemm_fp16_kernel,
                         cudaFuncAttributeMaxDynamicSharedMemorySize, SMEM_BYTES);
    dim3 grid(N / BN, M / BM);
    gemm_fp16_kernel<<<grid, 128, SMEM_BYTES>>>(A, lda, Bw, bias, C, Ch, M, N, K);
}

static void launch_thalf(const float* src, __half* dst, int rows, int cols)
{
    dim3 grid(cols / 32, rows / 32), blk(32, 8);
    transpose_half<<<grid, blk>>>(src, dst, rows, cols);
}

static void launch_copy(const float* s, float* d, int n)
{
    copyf<<<(n + 255) / 256, 256>>>(s, d, n);
}

extern "C" void kernel_launch(void* const* d_in, const int* in_sizes, int n_in,
                              void* d_out, int out_size)
{
    const float* h_t  = (const float*)d_in[0];
    const float* Wc   = (const float*)d_in[1];
    const float* bc   = (const float*)d_in[2];
    const float* Wcq  = (const float*)d_in[3];
    const float* bcq  = (const float*)d_in[4];
    const float* Wqr  = (const float*)d_in[5];
    const float* bqr  = (const float*)d_in[6];
    const float* Wckv = (const float*)d_in[7];
    const float* bckv = (const float*)d_in[8];
    const float* Wck  = (const float*)d_in[9];
    const float* bck  = (const float*)d_in[10];
    const float* Wkr  = (const float*)d_in[11];
    const float* bkr  = (const float*)d_in[12];
    const float* Wv   = (const float*)d_in[13];
    const float* bv   = (const float*)d_in[14];
    const float* Wo   = (const float*)d_in[15];
    const float* bo   = (const float*)d_in[16];
    float* out = (float*)d_out;

    float *b1, *b2, *b3;
    __half *s1h, *s2h, *s3h, *hth, *obh, *w1, *w2, *w3, *w4;
    cudaGetSymbolAddress((void**)&s1h, g_s1h);
    cudaGetSymbolAddress((void**)&s2h, g_s2h);
    cudaGetSymbolAddress((void**)&s3h, g_s3h);
    cudaGetSymbolAddress((void**)&hth, g_hth);
    cudaGetSymbolAddress((void**)&obh, g_obh);
    cudaGetSymbolAddress((void**)&w1,  g_w1);
    cudaGetSymbolAddress((void**)&w2,  g_w2);
    cudaGetSymbolAddress((void**)&w3,  g_w3);
    cudaGetSymbolAddress((void**)&w4,  g_w4);
    cudaGetSymbolAddress((void**)&b1,  g_b1);
    cudaGetSymbolAddress((void**)&b2,  g_b2);
    cudaGetSymbolAddress((void**)&b3,  g_b3);

    // Pack: weights (transpose + fp16 round) and h_t (fp16 convert)
    launch_thalf(Wc,   w1 + (size_t)0    * 2048, 2048, 512);
    launch_thalf(Wckv, w1 + (size_t)512  * 2048, 2048, 512);
    launch_thalf(Wkr,  w1 + (size_t)1024 * 2048, 2048, 1024);
    launch_thalf(Wcq,  w2 + (size_t)0    * 512,  512, 2048);
    launch_thalf(Wqr,  w2 + (size_t)2048 * 512,  512, 1024);
    launch_thalf(Wck,  w3 + (size_t)0    * 512,  512, 2048);
    launch_thalf(Wv,   w3 + (size_t)2048 * 512,  512, 2048);
    launch_thalf(Wo,   w4, 2048, 2048);
    launch_copy(bc,   b1,        512);
    launch_copy(bckv, b1 + 512,  512);
    launch_copy(bkr,  b1 + 1024, 1024);
    launch_copy(bcq,  b2,        2048);
    launch_copy(bqr,  b2 + 2048, 1024);
    launch_copy(bck,  b3,        2048);
    launch_copy(bv,   b3 + 2048, 2048);
    {
        int n = MTOK * 2048;
        convert_kernel<<<(n / 4 + 255) / 256, 256>>>(h_t, hth, n);
    }

    // G1: h_t -> (cq|ckv|kr), fp16 only
    launch_gemm(hth, 2048, w1, b1, nullptr, s1h, MTOK, 2048, 2048);
    // G2: cq -> (q|qr), fp16 only
    launch_gemm(s1h, 2048, w2, b2, nullptr, s2h, MTOK, 3072, 512);
    // G3: ckv -> (k|v), fp16 only
    launch_gemm(s1h + 512, 2048, w3, b3, nullptr, s3h, MTOK, 4096, 512);
    // attention (fp16 in/out, fp32 math)
    attn_kernel<<<MTOK, 256>>>(s1h, s2h, s3h, obh);
    // G4: o -> out (fp32 output)
    launch_gemm(obh, 2048, w4, bo, out, nullptr, MTOK, 2048, 2048);
}

// round 17
// speedup vs baseline: 2.5876x; 1.0232x over previous
#include <cuda_runtime.h>
#include <cuda_fp16.h>
#include <math.h>
#include <stdint.h>

// ---------------------------------------------------------------------------
// Problem constants
// ---------------------------------------------------------------------------
#define BB 2
#define SS 4096
#define HH 16
#define DKQV 2048
#define DH 128
#define DRH 64
#define MTOK (BB*SS)            // 8192 tokens

// ---------------------------------------------------------------------------
// Device scratch (fp16 everywhere except final output)
// ---------------------------------------------------------------------------
__device__ __half g_s1h[MTOK * 2048];                      // cq | ckv | kr
__device__ __half g_s2h[MTOK * 3072];                      // q | qr
__device__ __half g_s3h[MTOK * 4096];                      // k | v
__device__ __half g_hth[MTOK * 2048];                      // h_t fp16
__device__ __half g_obh[MTOK * 2048];                      // attn out fp16
__device__ __half g_w1[2048 * 2048];                       // (Wc|Wckv|Wkr)^T fp16
__device__ __half g_w2[3072 * 512];                        // (Wcq|Wqr)^T
__device__ __half g_w3[4096 * 512];                        // (Wck|Wv)^T
__device__ __half g_w4[2048 * 2048];                       // Wo^T
__device__ float g_b1 [2048];
__device__ float g_b2 [3072];
__device__ float g_b3 [4096];
__device__ float g_ropec[SS * 32];                         // cos table
__device__ float g_ropes[SS * 32];                         // sin table

// ---------------------------------------------------------------------------
// GEMM config: CTA 128x128, BK=32, 128 threads (4 warps of 64x64), 2 stages
// fp16 tiles [128 rows][32 k] in smem, row stride 20 u32 (16 data + 4 pad).
// ---------------------------------------------------------------------------
#define BM 128
#define BN 128
#define BK 32
#define TSTRIDE 20
#define TILE_B (128 * TSTRIDE * 4)      // 10240 bytes
#define STAGE_B (2 * TILE_B)            // A, B = 20480
#define SMEM_BYTES (2 * STAGE_B)        // 40960 -> 2 CTAs/SM

__device__ __forceinline__ uint32_t smem_u32(const void* p) {
    uint32_t a;
    asm("{ .reg .u64 t; cvta.to.shared.u64 t, %1; cvt.u32.u64 %0, t; }"
        : "=r"(a) : "l"(p));
    return a;
}
__device__ __forceinline__ void cp_async16(uint32_t dst, const void* src) {
    asm volatile("cp.async.cg.shared.global [%0], [%1], 16;"
                 :: "r"(dst), "l"(src) : "memory");
}
__device__ __forceinline__ void cp_commit() {
    asm volatile("cp.async.commit_group;" ::: "memory");
}
__device__ __forceinline__ void cp_wait1() {
    asm volatile("cp.async.wait_group 1;" ::: "memory");
}

__device__ __forceinline__ void mma_fp16(float c[4], uint32_t a0, uint32_t a1,
                                         uint32_t a2, uint32_t a3,
                                         uint32_t b0, uint32_t b1) {
    asm volatile(
        "mma.sync.aligned.m16n8k16.row.col.f32.f16.f16.f32 "
        "{%0,%1,%2,%3}, {%4,%5,%6,%7}, {%8,%9}, {%0,%1,%2,%3};"
        : "+f"(c[0]), "+f"(c[1]), "+f"(c[2]), "+f"(c[3])
        : "r"(a0), "r"(a1), "r"(a2), "r"(a3), "r"(b0), "r"(b1));
}

__device__ __forceinline__ void ldsm_x4(uint32_t& r0, uint32_t& r1,
                                        uint32_t& r2, uint32_t& r3,
                                        uint32_t addr) {
    asm volatile("ldmatrix.sync.aligned.m8n8.x4.shared.b16 {%0,%1,%2,%3}, [%4];"
                 : "=r"(r0), "=r"(r1), "=r"(r2), "=r"(r3) : "r"(addr));
}

// fp16 [row,K] tile (128 rows x 32 cols = 64B/row) -> smem [128][20 u32]
__device__ __forceinline__ void tile_async(const __half* __restrict__ g,
                                           int ld, uint32_t sbase, int tid) {
#pragma unroll
    for (int j = 0; j < 4; j++) {
        int idx = tid + j * 128;       // 0..511
        int r = idx >> 2, c = idx & 3; // 4 x 16B chunks per row
        cp_async16(sbase + (uint32_t)(r * TSTRIDE + c * 4) * 4,
                   g + (size_t)r * ld + c * 8);
    }
}

// ---------------------------------------------------------------------------
// fp16 GEMM: C = A[M,K] @ B[N,K]^T + bias, fp32 accumulate.
// Emits fp32 C (if non-null) and/or fp16 Ch (if non-null).
// grid(N/128, M/128), 128 thr.
// ---------------------------------------------------------------------------
__global__ void __launch_bounds__(128, 2) gemm_fp16_kernel(
    const __half* __restrict__ A, int lda,
    const __half* __restrict__ Bw,
    const float* __restrict__ bias,
    float* __restrict__ C,         // may be null
    __half* __restrict__ Ch,       // may be null
    int M, int N, int K)
{
    extern __shared__ float smem[];
    const uint32_t sb = smem_u32(smem);
    const int tid = threadIdx.x;
    const int lane = tid & 31;
    const int wid = tid >> 5;
    const int g = lane >> 2;
    const int t = lane & 3;
    const int wm = (wid & 1) * 64;
    const int wn = (wid >> 1) * 64;

    const int lrow = lane & 7;
    const int lsel = lane >> 3;
    const int a_row = wm + (lsel & 1) * 8 + lrow;
    const int a_col = (lsel >> 1) * 4;
    const int b_row = wn + (lsel >> 1) * 8 + lrow;
    const int b_col = (lsel & 1) * 4;

    const int m0 = blockIdx.y * BM;
    const int n0 = blockIdx.x * BN;
    const __half* Aptr = A + (size_t)m0 * lda;
    const __half* Bptr = Bw + (size_t)n0 * K;

    float acc[4][8][4];
#pragma unroll
    for (int mf = 0; mf < 4; mf++)
#pragma unroll
        for (int nf = 0; nf < 8; nf++)
#pragma unroll
            for (int r = 0; r < 4; r++) acc[mf][nf][r] = 0.f;

    const int NC = K / BK;

#pragma unroll
    for (int p = 0; p < 2; p++) {
        const uint32_t st = sb + p * STAGE_B;
        tile_async(Aptr + p * BK, lda, st, tid);
        tile_async(Bptr + p * BK, K, st + TILE_B, tid);
        cp_commit();
    }

    for (int i = 0; i < NC; i++) {
        cp_wait1();
        __syncthreads();
        const int s = i & 1;
        const uint32_t stA = sb + s * STAGE_B;
        const uint32_t stB = stA + TILE_B;
        const uint32_t aoff = (uint32_t)(a_row * TSTRIDE + a_col) * 4;
        const uint32_t boff = (uint32_t)(b_row * TSTRIDE + b_col) * 4;

#pragma unroll
        for (int ks = 0; ks < 2; ks++) {
            const uint32_t kb = (uint32_t)(ks * 8) * 4;
            uint32_t a[4][4], b[8][2];
#pragma unroll
            for (int mf = 0; mf < 4; mf++) {
                const uint32_t ao = (uint32_t)(mf * 16 * TSTRIDE) * 4 + kb;
                ldsm_x4(a[mf][0], a[mf][1], a[mf][2], a[mf][3],
                        stA + aoff + ao);
            }
#pragma unroll
            for (int p = 0; p < 4; p++) {
                const uint32_t bo = (uint32_t)(p * 16 * TSTRIDE) * 4 + kb;
                ldsm_x4(b[2*p][0], b[2*p][1], b[2*p+1][0], b[2*p+1][1],
                        stB + boff + bo);
            }
#pragma unroll
            for (int mf = 0; mf < 4; mf++)
#pragma unroll
                for (int nf = 0; nf < 8; nf++)
                    mma_fp16(acc[mf][nf], a[mf][0], a[mf][1], a[mf][2],
                             a[mf][3], b[nf][0], b[nf][1]);
        }
        __syncthreads();
        if (i + 2 < NC) {
            const int k0 = (i + 2) * BK;
            const uint32_t st = sb + s * STAGE_B;
            tile_async(Aptr + k0, lda, st, tid);
            tile_async(Bptr + k0, K, st + TILE_B, tid);
        }
        cp_commit();
    }

    // Epilogue
    const bool emitf = (C != nullptr);
    const bool emith = (Ch != nullptr);
#pragma unroll
    for (int mf = 0; mf < 4; mf++) {
        const int row0 = m0 + wm + mf * 16 + g;
#pragma unroll
        for (int nf = 0; nf < 8; nf++) {
            const int col = n0 + wn + nf * 8 + 2 * t;
            const float b0 = bias[col], b1 = bias[col + 1];
            float v00 = acc[mf][nf][0] + b0, v01 = acc[mf][nf][1] + b1;
            float v10 = acc[mf][nf][2] + b0, v11 = acc[mf][nf][3] + b1;
            if (emitf) {
                *(float2*)(C + (size_t)row0 * N + col) = make_float2(v00, v01);
                *(float2*)(C + (size_t)(row0 + 8) * N + col) = make_float2(v10, v11);
            }
            if (emith) {
                *(__half2*)(Ch + (size_t)row0 * N + col) =
                    __halves2half2(__float2half_rn(v00), __float2half_rn(v01));
                *(__half2*)(Ch + (size_t)(row0 + 8) * N + col) =
                    __halves2half2(__float2half_rn(v10), __float2half_rn(v11));
            }
        }
    }
}

// ---------------------------------------------------------------------------
// Fused weight pack: 8 transposes (fp32 [rows,cols] -> fp16 [cols,rows])
// in ONE launch, table-driven.
// ---------------------------------------------------------------------------
struct TPack {
    const float* src[8];
    __half* dst[8];
    int rows[8], cols[8];
    int blk0[9];           // cumulative block offsets
};

__global__ void pack_weights(TPack D)
{
    __shared__ float tile[32][33];
    int b = blockIdx.x;
    int seg = 0;
#pragma unroll
    for (int k = 1; k < 8; k++) seg += (b >= D.blk0[k]);
    const int lb = b - D.blk0[seg];
    const int rows = D.rows[seg], cols = D.cols[seg];
    const int nbx = cols >> 5;
    const int bx = lb % nbx, by = lb / nbx;
    const float* src = D.src[seg];
    __half* dst = D.dst[seg];

    const int c0 = bx * 32, r0 = by * 32;
    for (int i = threadIdx.y; i < 32; i += 8)
        tile[i][threadIdx.x] = src[(size_t)(r0 + i) * cols + c0 + threadIdx.x];
    __syncthreads();
    for (int i = threadIdx.y; i < 32; i += 8)
        dst[(size_t)(c0 + i) * rows + r0 + threadIdx.x] =
            __float2half_rn(tile[threadIdx.x][i]);
}

// ---------------------------------------------------------------------------
// Fused bias pack: 7 fp32 copies in one launch.
// ---------------------------------------------------------------------------
struct BPack {
    const float* src[7];
    float* dst[7];
    int off[8];            // cumulative element offsets
};

__global__ void pack_bias(BPack D)
{
    int idx = blockIdx.x * 256 + threadIdx.x;
    if (idx >= D.off[7]) return;
    int seg = 0;
#pragma unroll
    for (int k = 1; k < 7; k++) seg += (idx >= D.off[k]);
    int j = idx - D.off[seg];
    D.dst[seg][j] = D.src[seg][j];
}

// ---------------------------------------------------------------------------
// Elementwise fp32 -> fp16 convert (for h_t)
// ---------------------------------------------------------------------------
__global__ void convert_kernel(const float* __restrict__ src,
                               __half* __restrict__ dst, int n)
{
    int i = (blockIdx.x * 256 + threadIdx.x) * 4;
    if (i >= n) return;
    float4 v = *(const float4*)(src + i);
    *(__half2*)(dst + i)     = __halves2half2(__float2half_rn(v.x),
                                              __float2half_rn(v.y));
    *(__half2*)(dst + i + 2) = __halves2half2(__float2half_rn(v.z),
                                              __float2half_rn(v.w));
}

// ---------------------------------------------------------------------------
// Rope table: cos/sin for all (position, pair) combos. SS*32 entries.
// ---------------------------------------------------------------------------
__global__ void rope_table(float* __restrict__ rc, float* __restrict__ rs)
{
    const float LOG1E4 = 9.210340371976184f;
    int idx = blockIdx.x * 256 + threadIdx.x;
    if (idx >= SS * 32) return;
    int s = idx >> 5, j = idx & 31;
    float invf = expf(-LOG1E4 * ((float)(2 * j) / 64.0f));
    float ang = (float)s * invf;
    float sj, cj;
    sincosf(ang, &sj, &cj);
    rc[idx] = cj;
    rs[idx] = sj;
}

// ---------------------------------------------------------------------------
// Per-token attention (rope via table). 256 threads / token.
// fp16 in/out, fp32 math.
// ---------------------------------------------------------------------------
#define QK_STRIDE 193

__global__ void __launch_bounds__(256) attn_kernel(
    const __half* __restrict__ s1h, const __half* __restrict__ s2h,
    const __half* __restrict__ s3h,
    const float* __restrict__ ropec, const float* __restrict__ ropes,
    __half* __restrict__ obh)
{
    const float SCALER = 1.0f / sqrtf((float)(DH + DRH));

    int tk = blockIdx.x;
    int s = tk & (SS - 1);
    int tid = threadIdx.x;

    __shared__ float qf[HH][QK_STRIDE];
    __shared__ float kf[HH][QK_STRIDE];
    __shared__ float vv[HH][DH];
    __shared__ float sc[HH][HH];
    __shared__ float at[HH][HH];

    const __half* qp  = s2h + (size_t)tk * 3072;
    const __half* qrp = qp + 2048;
    const __half* kp  = s3h + (size_t)tk * 4096;
    const __half* vp  = kp + 2048;
    const __half* krp = s1h + (size_t)tk * 2048 + 1024;

    for (int p = tid; p < HH * DH / 2; p += 256) {
        int idx = p * 2;
        int h = idx >> 7, d = idx & 127;
        float2 q2 = __half22float2(*(const __half2*)(qp + idx));
        float2 k2 = __half22float2(*(const __half2*)(kp + idx));
        float2 v2 = __half22float2(*(const __half2*)(vp + idx));
        qf[h][d] = q2.x; qf[h][d + 1] = q2.y;
        kf[h][d] = k2.x; kf[h][d + 1] = k2.y;
        vv[h][d] = v2.x; vv[h][d + 1] = v2.y;
    }
    for (int idx = tid; idx < HH * 32; idx += 256) {
        int h = idx >> 5, j = idx & 31;
        float cj = ropec[s * 32 + j];
        float sj = ropes[s * 32 + j];
        float x1q = __half2float(qrp[h * DRH + j]);
        float x2q = __half2float(qrp[h * DRH + j + 32]);
        qf[h][DH + j]      = x1q * cj - x2q * sj;
        qf[h][DH + j + 32] = x2q * cj + x1q * sj;
        float x1k = __half2float(krp[h * DRH + j]);
        float x2k = __half2float(krp[h * DRH + j + 32]);
        kf[h][DH + j]      = x1k * cj - x2k * sj;
        kf[h][DH + j + 32] = x2k * cj + x1k * sj;
    }
    __syncthreads();

    {
        int i = tid >> 4, j = tid & 15;
        float dsum = 0.f;
#pragma unroll 8
        for (int d = 0; d < DH + DRH; d++)
            dsum = fmaf(qf[i][d], kf[j][d], dsum);
        sc[i][j] = dsum * SCALER;
    }
    __syncthreads();

    if (tid < HH) {
        float mx = -1e30f;
#pragma unroll
        for (int j = 0; j < HH; j++) mx = fmaxf(mx, sc[tid][j]);
        float e[HH], sum = 0.f;
#pragma unroll
        for (int j = 0; j < HH; j++) { e[j] = expf(sc[tid][j] - mx); sum += e[j]; }
        float inv = 1.0f / sum;
#pragma unroll
        for (int j = 0; j < HH; j++) at[tid][j] = e[j] * inv;
    }
    __syncthreads();

    for (int p = tid; p < HH * DH / 2; p += 256) {
        int idx = p * 2;
        int i = idx >> 7, d = idx & 127;
        float a0 = 0.f, a1 = 0.f;
#pragma unroll
        for (int j = 0; j < HH; j++) {
            float w = at[i][j];
            a0 = fmaf(w, vv[j][d], a0);
            a1 = fmaf(w, vv[j][d + 1], a1);
        }
        *(__half2*)(obh + (size_t)tk * DKQV + idx) =
            __halves2half2(__float2half_rn(a0), __float2half_rn(a1));
    }
}

// ---------------------------------------------------------------------------
// Launch
// ---------------------------------------------------------------------------
static void launch_gemm(const __half* A, int lda, const __half* Bw,
                        const float* bias, float* C, __half* Ch,
                        int M, int N, int K)
{
    cudaFuncSetAttribute(gemm_fp16_kernel,
                         cudaFuncAttributeMaxDynamicSharedMemorySize, SMEM_BYTES);
    dim3 grid(N / BN, M / BM);
    gemm_fp16_kernel<<<grid, 128, SMEM_BYTES>>>(A, lda, Bw, bias, C, Ch, M, N, K);
}

extern "C" void kernel_launch(void* const* d_in, const int* in_sizes, int n_in,
                              void* d_out, int out_size)
{
    const float* h_t  = (const float*)d_in[0];
    const float* Wc   = (const float*)d_in[1];
    const float* bc   = (const float*)d_in[2];
    const float* Wcq  = (const float*)d_in[3];
    const float* bcq  = (const float*)d_in[4];
    const float* Wqr  = (const float*)d_in[5];
    const float* bqr  = (const float*)d_in[6];
    const float* Wckv = (const float*)d_in[7];
    const float* bckv = (const float*)d_in[8];
    const float* Wck  = (const float*)d_in[9];
    const float* bck  = (const float*)d_in[10];
    const float* Wkr  = (const float*)d_in[11];
    const float* bkr  = (const float*)d_in[12];
    const float* Wv   = (const float*)d_in[13];
    const float* bv   = (const float*)d_in[14];
    const float* Wo   = (const float*)d_in[15];
    const float* bo   = (const float*)d_in[16];
    float* out = (float*)d_out;

    float *b1, *b2, *b3, *ropec, *ropes;
    __half *s1h, *s2h, *s3h, *hth, *obh, *w1, *w2, *w3, *w4;
    cudaGetSymbolAddress((void**)&s1h, g_s1h);
    cudaGetSymbolAddress((void**)&s2h, g_s2h);
    cudaGetSymbolAddress((void**)&s3h, g_s3h);
    cudaGetSymbolAddress((void**)&hth, g_hth);
    cudaGetSymbolAddress((void**)&obh, g_obh);
    cudaGetSymbolAddress((void**)&w1,  g_w1);
    cudaGetSymbolAddress((void**)&w2,  g_w2);
    cudaGetSymbolAddress((void**)&w3,  g_w3);
    cudaGetSymbolAddress((void**)&w4,  g_w4);
    cudaGetSymbolAddress((void**)&b1,  g_b1);
    cudaGetSymbolAddress((void**)&b2,  g_b2);
    cudaGetSymbolAddress((void**)&b3,  g_b3);
    cudaGetSymbolAddress((void**)&ropec, g_ropec);
    cudaGetSymbolAddress((void**)&ropes, g_ropes);

    // --- Fused weight pack (8 transposes, one launch) ---
    TPack tp;
    const float* srcs[8] = { Wc, Wckv, Wkr, Wcq, Wqr, Wck, Wv, Wo };
    __half* dsts[8] = { w1, w1 + (size_t)512 * 2048, w1 + (size_t)1024 * 2048,
                        w2, w2 + (size_t)2048 * 512,
                        w3, w3 + (size_t)2048 * 512, w4 };
    int rws[8] = { 2048, 2048, 2048, 512, 512, 512, 512, 2048 };
    int cls[8] = { 512, 512, 1024, 2048, 1024, 2048, 2048, 2048 };
    int acc = 0;
    for (int k = 0; k < 8; k++) {
        tp.src[k] = srcs[k];
        tp.dst[k] = dsts[k];
        tp.rows[k] = rws[k];
        tp.cols[k] = cls[k];
        tp.blk0[k] = acc;
        acc += (rws[k] / 32) * (cls[k] / 32);
    }
    tp.blk0[8] = acc;
    pack_weights<<<acc, dim3(32, 8)>>>(tp);

    // --- Fused bias pack (7 copies, one launch) ---
    BPack bp;
    const float* bsrc[7] = { bc, bckv, bkr, bcq, bqr, bck, bv };
    float* bdst[7] = { b1, b1 + 512, b1 + 1024, b2, b2 + 2048, b3, b3 + 2048 };
    int bn[7] = { 512, 512, 1024, 2048, 1024, 2048, 2048 };
    int bacc = 0;
    for (int k = 0; k < 7; k++) {
        bp.src[k] = bsrc[k];
        bp.dst[k] = bdst[k];
        bp.off[k] = bacc;
        bacc += bn[k];
    }
    bp.off[7] = bacc;
    pack_bias<<<(bacc + 255) / 256, 256>>>(bp);

    // --- h_t convert + rope table ---
    {
        int n = MTOK * 2048;
        convert_kernel<<<(n / 4 + 255) / 256, 256>>>(h_t, hth, n);
    }
    rope_table<<<(SS * 32 + 255) / 256, 256>>>(ropec, ropes);

    // G1: h_t -> (cq|ckv|kr), fp16 only
    launch_gemm(hth, 2048, w1, b1, nullptr, s1h, MTOK, 2048, 2048);
    // G2: cq -> (q|qr), fp16 only
    launch_gemm(s1h, 2048, w2, b2, nullptr, s2h, MTOK, 3072, 512);
    // G3: ckv -> (k|v), fp16 only
    launch_gemm(s1h + 512, 2048, w3, b3, nullptr, s3h, MTOK, 4096, 512);
    // attention (fp16 in/out, fp32 math, rope table)
    attn_kernel<<<MTOK, 256>>>(s1h, s2h, s3h, ropec, ropes, obh);
    // G4: o -> out (fp32 output)
    launch_gemm(obh, 2048, w4, bo, out, nullptr, MTOK, 2048, 2048);
}